// round 4
// baseline (speedup 1.0000x reference)
#include <cuda_runtime.h>

// ---------------------------------------------------------------------------
// AllocationGNN: 3x GATConv + MLP head.
// Inputs (metadata order):
//  0 x[N,256] f32, 1 edge_index[2,E] int32 (JAX default x64-disabled!),
//  2 W1[512,256], 3 a_src1[4,128], 4 a_dst1[4,128], 5 b1[512],
//  6 W2[512,512], 7 a_src2[4,128], 8 a_dst2[4,128], 9 b2[512],
//  10 W3[128,512], 11 a_src3[1,128], 12 a_dst3[1,128], 13 b3[128],
//  14 Wh1[64,128], 15 bh1[64], 16 Wh2[1,64], 17 bh2[1]
// Output: embeddings[N*128] then scores[N]  (6,450,000 f32)
// ---------------------------------------------------------------------------

#define NMAX 50000
#define EMAX 800000
#define ETMAX (EMAX + NMAX)

// scratch — declared as float4 so 16B alignment is guaranteed by type
__device__ float4   g_h_buf4[(size_t)NMAX * 128];    // N*512 floats
__device__ float4   g_out_buf4[(size_t)NMAX * 128];  // N*512 floats
__device__ float    g_sn_buf[NMAX * 4];
__device__ float    g_dn_buf[NMAX * 4];
__device__ unsigned g_m_buf[NMAX * 4];
__device__ float    g_den_buf[NMAX * 4];
__device__ float4   g_e_buf4[(size_t)ETMAX];         // ET*4 floats

// ---- helpers ---------------------------------------------------------------

__device__ __forceinline__ unsigned fenc(float f) {
    unsigned b = __float_as_uint(f);
    return (b & 0x80000000u) ? ~b : (b | 0x80000000u);
}
__device__ __forceinline__ float fdec(unsigned k) {
    return (k & 0x80000000u) ? __uint_as_float(k ^ 0x80000000u)
                             : __uint_as_float(~k);
}

__device__ __forceinline__ void red_add_v4(float* p, float4 v) {
    asm volatile("red.global.add.v4.f32 [%0], {%1,%2,%3,%4};"
                 :: "l"(p), "f"(v.x), "f"(v.y), "f"(v.z), "f"(v.w)
                 : "memory");
}

// ---- fill kernels ----------------------------------------------------------

__global__ void fill_f32(float* p, float v, int n) {
    int i = blockIdx.x * blockDim.x + threadIdx.x;
    if (i < n) p[i] = v;
}
__global__ void fill_u32(unsigned* p, unsigned v, int n) {
    int i = blockIdx.x * blockDim.x + threadIdx.x;
    if (i < n) p[i] = v;
}

// ---- SGEMM: C[M,N] = A[M,K] * B[N,K]^T  (both row-major, K contiguous) -----

__global__ __launch_bounds__(256, 2)
void sgemm_nt(const float* __restrict__ A, const float* __restrict__ B,
              float* __restrict__ Cm, int M, int N, int K) {
    constexpr int BM = 128, BN = 128, BK = 16;
    __shared__ float As[BK][BM];
    __shared__ float Bs[BK][BN];
    const int tid = threadIdx.x;
    const int bm = blockIdx.y * BM, bn = blockIdx.x * BN;
    const int tr = tid >> 4, tc = tid & 15;   // 16x16 thread tile, 8x8 micro
    float acc[8][8] = {};

    for (int k0 = 0; k0 < K; k0 += BK) {
        #pragma unroll
        for (int i = 0; i < 2; i++) {
            int idx = tid + (i << 8);       // 0..511
            int r = idx >> 2, c4 = idx & 3; // tile row, float4 column
            float4 va = make_float4(0.f, 0.f, 0.f, 0.f);
            float4 vb = make_float4(0.f, 0.f, 0.f, 0.f);
            int gm = bm + r;
            if (gm < M)
                va = *reinterpret_cast<const float4*>(A + (size_t)gm * K + k0 + c4 * 4);
            int gn = bn + r;
            if (gn < N)
                vb = *reinterpret_cast<const float4*>(B + (size_t)gn * K + k0 + c4 * 4);
            As[c4 * 4 + 0][r] = va.x; As[c4 * 4 + 1][r] = va.y;
            As[c4 * 4 + 2][r] = va.z; As[c4 * 4 + 3][r] = va.w;
            Bs[c4 * 4 + 0][r] = vb.x; Bs[c4 * 4 + 1][r] = vb.y;
            Bs[c4 * 4 + 2][r] = vb.z; Bs[c4 * 4 + 3][r] = vb.w;
        }
        __syncthreads();
        #pragma unroll
        for (int k = 0; k < BK; k++) {
            float4 a0 = *reinterpret_cast<const float4*>(&As[k][tr * 8]);
            float4 a1 = *reinterpret_cast<const float4*>(&As[k][tr * 8 + 4]);
            float4 b0 = *reinterpret_cast<const float4*>(&Bs[k][tc * 8]);
            float4 b1 = *reinterpret_cast<const float4*>(&Bs[k][tc * 8 + 4]);
            float a[8] = {a0.x, a0.y, a0.z, a0.w, a1.x, a1.y, a1.z, a1.w};
            float b[8] = {b0.x, b0.y, b0.z, b0.w, b1.x, b1.y, b1.z, b1.w};
            #pragma unroll
            for (int i = 0; i < 8; i++)
                #pragma unroll
                for (int j = 0; j < 8; j++)
                    acc[i][j] += a[i] * b[j];
        }
        __syncthreads();
    }
    #pragma unroll
    for (int i = 0; i < 8; i++) {
        int gm = bm + tr * 8 + i;
        if (gm < M) {
            float* crow = Cm + (size_t)gm * N + bn + tc * 8;
            #pragma unroll
            for (int j = 0; j < 8; j += 4) {
                float4 v = make_float4(acc[i][j], acc[i][j + 1],
                                       acc[i][j + 2], acc[i][j + 3]);
                *reinterpret_cast<float4*>(crow + j) = v;
            }
        }
    }
}

// ---- attention coefficients: s_n, d_n  (one warp per (node, head)) ---------

__global__ void compute_sd(const float* __restrict__ h,
                           const float* __restrict__ a_src,
                           const float* __restrict__ a_dst,
                           float* __restrict__ sn, float* __restrict__ dn,
                           int N, int H, int C) {
    int w = (blockIdx.x * blockDim.x + threadIdx.x) >> 5;
    int lane = threadIdx.x & 31;
    if (w >= N * H) return;
    int n = w / H, hh = w % H;
    const float* row = h + (size_t)n * H * C + hh * C;
    const float* as = a_src + hh * C;
    const float* ad = a_dst + hh * C;
    float s = 0.f, d = 0.f;
    for (int c = lane; c < C; c += 32) {
        float v = row[c];
        s += v * as[c];
        d += v * ad[c];
    }
    #pragma unroll
    for (int o = 16; o; o >>= 1) {
        s += __shfl_down_sync(0xffffffffu, s, o);
        d += __shfl_down_sync(0xffffffffu, d, o);
    }
    if (lane == 0) { sn[w] = s; dn[w] = d; }
}

// ---- edge pass 1: e = leaky_relu(s[src]+d[dst]); segment max ---------------

template <int H>
__global__ void edge_pass1(const int* __restrict__ ei,
                           const float* __restrict__ sn,
                           const float* __restrict__ dn,
                           float* __restrict__ ebuf,
                           unsigned* __restrict__ menc, int E, int N) {
    int eid = blockIdx.x * blockDim.x + threadIdx.x;
    if (eid >= E + N) return;
    int src, dst;
    if (eid < E) { src = ei[eid]; dst = ei[E + eid]; }
    else         { src = dst = eid - E; }
    #pragma unroll
    for (int h = 0; h < H; h++) {
        float e = sn[src * H + h] + dn[dst * H + h];
        e = e > 0.f ? e : 0.2f * e;
        ebuf[eid * H + h] = e;
        atomicMax(&menc[dst * H + h], fenc(e));
    }
}

// ---- edge pass 2: ex = exp(e - m[dst]); segment sum ------------------------

template <int H>
__global__ void edge_pass2(const int* __restrict__ ei,
                           float* __restrict__ ebuf,
                           const unsigned* __restrict__ menc,
                           float* __restrict__ den, int E, int N) {
    int eid = blockIdx.x * blockDim.x + threadIdx.x;
    if (eid >= E + N) return;
    int dst;
    if (eid < E) dst = ei[E + eid];
    else         dst = eid - E;
    #pragma unroll
    for (int h = 0; h < H; h++) {
        float m = fdec(menc[dst * H + h]);
        float ex = __expf(ebuf[eid * H + h] - m);
        ebuf[eid * H + h] = ex;
        atomicAdd(&den[dst * H + h], ex);
    }
}

// ---- edge pass 3: out[dst] += alpha * h[src]  (float4 reductions) ----------

template <int H, int C>
__global__ void edge_pass3(const int* __restrict__ ei,
                           const float4* __restrict__ hf,
                           const float* __restrict__ ebuf,
                           const float* __restrict__ den,
                           float4* __restrict__ outp, int E, int N, int tot) {
    constexpr int J = H * C / 4;
    int t = blockIdx.x * blockDim.x + threadIdx.x;
    if (t >= tot) return;
    int eid = t / J, j = t % J;
    int src, dst;
    if (eid < E) { src = ei[eid]; dst = ei[E + eid]; }
    else         { src = dst = eid - E; }
    int h = (j * 4) / C;
    float alpha = ebuf[eid * H + h] / (den[dst * H + h] + 1e-16f);
    float4 v = __ldg(hf + (size_t)src * J + j);
    v.x *= alpha; v.y *= alpha; v.z *= alpha; v.w *= alpha;
    red_add_v4(reinterpret_cast<float*>(outp + (size_t)dst * J + j), v);
}

// ---- epilogue: bias + optional ELU ----------------------------------------

__global__ void bias_act(const float* __restrict__ in, const float* __restrict__ b,
                         float* __restrict__ out, int total, int D, int act) {
    int t = blockIdx.x * blockDim.x + threadIdx.x;
    if (t >= total) return;
    float v = in[t] + b[t % D];
    if (act) v = v > 0.f ? v : (__expf(v) - 1.f);
    out[t] = v;
}

// ---- MLP head: scores = sigmoid(relu(emb@Wh1^T+bh1)@Wh2^T+bh2) -------------

__global__ __launch_bounds__(64)
void head_kernel(const float* __restrict__ emb, const float* __restrict__ Wh1,
                 const float* __restrict__ bh1, const float* __restrict__ Wh2,
                 const float* __restrict__ bh2, float* __restrict__ scores, int N) {
    int n = blockIdx.x;
    int j = threadIdx.x;  // 64 threads
    __shared__ float er[128];
    __shared__ float zs[64];
    er[j]      = emb[(size_t)n * 128 + j];
    er[j + 64] = emb[(size_t)n * 128 + 64 + j];
    __syncthreads();
    const float* w = Wh1 + j * 128;
    float s = 0.f;
    #pragma unroll 8
    for (int k = 0; k < 128; k++) s += er[k] * w[k];
    s += bh1[j];
    s = fmaxf(s, 0.f);
    zs[j] = s * Wh2[j];
    __syncthreads();
    if (j < 32) {
        float v = zs[j] + zs[j + 32];
        #pragma unroll
        for (int o = 16; o; o >>= 1) v += __shfl_down_sync(0xffffffffu, v, o);
        if (j == 0) scores[n] = 1.f / (1.f + __expf(-(v + bh2[0])));
    }
}

// ---------------------------------------------------------------------------

extern "C" void kernel_launch(void* const* d_in, const int* in_sizes, int n_in,
                              void* d_out, int out_size) {
    const float* x  = (const float*)d_in[0];
    const int*   ei = (const int*)d_in[1];   // int32! (JAX x64 disabled)
    const float *W1 = (const float*)d_in[2],  *as1 = (const float*)d_in[3],
                *ad1 = (const float*)d_in[4], *b1 = (const float*)d_in[5];
    const float *W2 = (const float*)d_in[6],  *as2 = (const float*)d_in[7],
                *ad2 = (const float*)d_in[8], *b2 = (const float*)d_in[9];
    const float *W3 = (const float*)d_in[10], *as3 = (const float*)d_in[11],
                *ad3 = (const float*)d_in[12], *b3 = (const float*)d_in[13];
    const float *Wh1 = (const float*)d_in[14], *bh1 = (const float*)d_in[15],
                *Wh2 = (const float*)d_in[16], *bh2 = (const float*)d_in[17];
    float* out = (float*)d_out;

    const int N = in_sizes[0] / 256;
    const int E = in_sizes[1] / 2;
    const int ET = E + N;

    float4 *gh4, *gout4, *ebuf4;
    float *snp, *dnp, *den;
    unsigned* menc;
    cudaGetSymbolAddress((void**)&gh4,   g_h_buf4);
    cudaGetSymbolAddress((void**)&gout4, g_out_buf4);
    cudaGetSymbolAddress((void**)&snp,   g_sn_buf);
    cudaGetSymbolAddress((void**)&dnp,   g_dn_buf);
    cudaGetSymbolAddress((void**)&menc,  g_m_buf);
    cudaGetSymbolAddress((void**)&den,   g_den_buf);
    cudaGetSymbolAddress((void**)&ebuf4, g_e_buf4);
    float* gh   = (float*)gh4;
    float* gout = (float*)gout4;
    float* ebuf = (float*)ebuf4;

    auto cdiv = [](int a, int b) { return (a + b - 1) / b; };

    // ---- generic GAT layer driver ----
    auto run_layer = [&](const float* fin, int Fin, const float* W,
                         const float* as, const float* ad, const float* bb,
                         int H, int C, int act, float* finalout) {
        const int HC = H * C;
        // 1) transform  (runs before gout is re-zeroed; stream order is safe)
        dim3 gg(cdiv(HC, 128), cdiv(N, 128));
        sgemm_nt<<<gg, 256>>>(fin, W, gh, N, HC, Fin);
        // 2) init segment buffers + output accumulator
        int nh = N * H;
        fill_u32<<<cdiv(nh, 256), 256>>>(menc, 0u, nh);
        fill_f32<<<cdiv(nh, 256), 256>>>(den, 0.f, nh);
        fill_f32<<<cdiv(N * HC, 256), 256>>>(gout, 0.f, N * HC);
        // 3) per-node attention coefficients
        compute_sd<<<cdiv(nh * 32, 256), 256>>>(gh, as, ad, snp, dnp, N, H, C);
        // 4-6) edge passes
        if (H == 4) {
            edge_pass1<4><<<cdiv(ET, 256), 256>>>(ei, snp, dnp, ebuf, menc, E, N);
            edge_pass2<4><<<cdiv(ET, 256), 256>>>(ei, ebuf, menc, den, E, N);
            int tot = ET * (4 * 128 / 4);
            edge_pass3<4, 128><<<cdiv(tot, 256), 256>>>(ei, gh4, ebuf, den, gout4, E, N, tot);
        } else {
            edge_pass1<1><<<cdiv(ET, 256), 256>>>(ei, snp, dnp, ebuf, menc, E, N);
            edge_pass2<1><<<cdiv(ET, 256), 256>>>(ei, ebuf, menc, den, E, N);
            int tot = ET * (1 * 128 / 4);
            edge_pass3<1, 128><<<cdiv(tot, 256), 256>>>(ei, gh4, ebuf, den, gout4, E, N, tot);
        }
        // 7) bias + activation
        bias_act<<<cdiv(N * HC, 256), 256>>>(gout, bb, finalout, N * HC, HC, act);
    };

    // layer 1: 256 -> 4x128 concat, ELU      (output in gout)
    run_layer(x, 256, W1, as1, ad1, b1, 4, 128, 1, gout);
    // layer 2: 512 -> 4x128 concat, ELU
    run_layer(gout, 512, W2, as2, ad2, b2, 4, 128, 1, gout);
    // layer 3: 512 -> 1x128, no concat (H=1 mean == identity), no activation,
    // embeddings written straight into d_out[0 .. N*128)
    run_layer(gout, 512, W3, as3, ad3, b3, 1, 128, 0, out);

    // MLP head -> scores at d_out[N*128 ..)
    head_kernel<<<N, 64>>>(out, Wh1, bh1, Wh2, bh2, out + (size_t)N * 128, N);
}

// round 9
// speedup vs baseline: 1.1963x; 1.1963x over previous
#include <cuda_runtime.h>
#include <cstdint>

// ---------------------------------------------------------------------------
// AllocationGNN: 3x GATConv + MLP head.
// Inputs (metadata order):
//  0 x[N,256] f32, 1 edge_index[2,E] int32,
//  2 W1[512,256], 3 a_src1[4,128], 4 a_dst1[4,128], 5 b1[512],
//  6 W2[512,512], 7 a_src2[4,128], 8 a_dst2[4,128], 9 b2[512],
//  10 W3[128,512], 11 a_src3[1,128], 12 a_dst3[1,128], 13 b3[128],
//  14 Wh1[64,128], 15 bh1[64], 16 Wh2[1,64], 17 bh2[1]
// Output: embeddings[N*128] then scores[N]
// R5: GEMMs moved from FFMA pipe to tensor pipe (mma.sync tf32).
// ---------------------------------------------------------------------------

#define NMAX 50000
#define EMAX 800000
#define ETMAX (EMAX + NMAX)

__device__ float4   g_h_buf4[(size_t)NMAX * 128];    // N*512 floats
__device__ float4   g_out_buf4[(size_t)NMAX * 128];  // N*512 floats
__device__ float    g_sn_buf[NMAX * 4];
__device__ float    g_dn_buf[NMAX * 4];
__device__ unsigned g_m_buf[NMAX * 4];
__device__ float    g_den_buf[NMAX * 4];
__device__ float4   g_e_buf4[(size_t)ETMAX];         // ET*4 floats

// ---- helpers ---------------------------------------------------------------

__device__ __forceinline__ unsigned fenc(float f) {
    unsigned b = __float_as_uint(f);
    return (b & 0x80000000u) ? ~b : (b | 0x80000000u);
}
__device__ __forceinline__ float fdec(unsigned k) {
    return (k & 0x80000000u) ? __uint_as_float(k ^ 0x80000000u)
                             : __uint_as_float(~k);
}
__device__ __forceinline__ void red_add_v4(float* p, float4 v) {
    asm volatile("red.global.add.v4.f32 [%0], {%1,%2,%3,%4};"
                 :: "l"(p), "f"(v.x), "f"(v.y), "f"(v.z), "f"(v.w)
                 : "memory");
}
__device__ __forceinline__ uint32_t f2tf32(float f) {
    uint32_t r;
    asm("cvt.rna.tf32.f32 %0, %1;" : "=r"(r) : "f"(f));
    return r;
}
__device__ __forceinline__ void mma_tf32(float* c, const uint32_t* a,
                                         const uint32_t* b) {
    asm volatile(
        "mma.sync.aligned.m16n8k8.row.col.f32.tf32.tf32.f32 "
        "{%0,%1,%2,%3}, {%4,%5,%6,%7}, {%8,%9}, {%0,%1,%2,%3};"
        : "+f"(c[0]), "+f"(c[1]), "+f"(c[2]), "+f"(c[3])
        : "r"(a[0]), "r"(a[1]), "r"(a[2]), "r"(a[3]), "r"(b[0]), "r"(b[1]));
}

// ---- fill kernels ----------------------------------------------------------

__global__ void fill_f32(float* p, float v, int n) {
    int i = blockIdx.x * blockDim.x + threadIdx.x;
    if (i < n) p[i] = v;
}
__global__ void fill_u32(unsigned* p, unsigned v, int n) {
    int i = blockIdx.x * blockDim.x + threadIdx.x;
    if (i < n) p[i] = v;
}

// ---- TF32 tensor-core GEMM: C[M,N] = A[M,K] * B[N,K]^T ---------------------
// Block 128x128x16, 8 warps, warp tile 64x32 (4x4 m16n8k8 fragments).
// Requires: K % 16 == 0, N % 128 == 0 (true here: K in {256,512}, N in {512,128}).

__global__ __launch_bounds__(256, 2)
void sgemm_tf32(const float* __restrict__ A, const float* __restrict__ B,
                float* __restrict__ Cm, int M, int N, int K) {
    constexpr int BM = 128, BN = 128, BK = 16, LDS = BK + 4;
    __shared__ uint32_t As[BM][LDS];
    __shared__ uint32_t Bs[BN][LDS];
    const int tid  = threadIdx.x;
    const int warp = tid >> 5, lane = tid & 31;
    const int wm = warp >> 2, wn = warp & 3;   // 2x4 warps -> 64x32 warp tiles
    const int g = lane >> 2, t4 = lane & 3;
    const int bm = blockIdx.y * BM, bn = blockIdx.x * BN;

    float c[4][4][4];
    #pragma unroll
    for (int mi = 0; mi < 4; mi++)
        #pragma unroll
        for (int ni = 0; ni < 4; ni++)
            #pragma unroll
            for (int q = 0; q < 4; q++) c[mi][ni][q] = 0.f;

    for (int k0 = 0; k0 < K; k0 += BK) {
        // load 128x16 of A and B (512 float4 each; 256 threads x 2)
        #pragma unroll
        for (int i = 0; i < 2; i++) {
            int idx = tid + (i << 8);          // 0..511
            int r = idx >> 2, c4 = (idx & 3) << 2;
            float4 va = make_float4(0.f, 0.f, 0.f, 0.f);
            if (bm + r < M)
                va = *reinterpret_cast<const float4*>(A + (size_t)(bm + r) * K + k0 + c4);
            As[r][c4 + 0] = f2tf32(va.x); As[r][c4 + 1] = f2tf32(va.y);
            As[r][c4 + 2] = f2tf32(va.z); As[r][c4 + 3] = f2tf32(va.w);
            float4 vb = *reinterpret_cast<const float4*>(B + (size_t)(bn + r) * K + k0 + c4);
            Bs[r][c4 + 0] = f2tf32(vb.x); Bs[r][c4 + 1] = f2tf32(vb.y);
            Bs[r][c4 + 2] = f2tf32(vb.z); Bs[r][c4 + 3] = f2tf32(vb.w);
        }
        __syncthreads();

        #pragma unroll
        for (int ks = 0; ks < BK; ks += 8) {
            uint32_t af[4][4], bf[4][2];
            #pragma unroll
            for (int mi = 0; mi < 4; mi++) {
                int row = wm * 64 + mi * 16;
                af[mi][0] = As[row + g][ks + t4];
                af[mi][1] = As[row + g + 8][ks + t4];
                af[mi][2] = As[row + g][ks + t4 + 4];
                af[mi][3] = As[row + g + 8][ks + t4 + 4];
            }
            #pragma unroll
            for (int ni = 0; ni < 4; ni++) {
                int col = wn * 32 + ni * 8;
                bf[ni][0] = Bs[col + g][ks + t4];
                bf[ni][1] = Bs[col + g][ks + t4 + 4];
            }
            #pragma unroll
            for (int mi = 0; mi < 4; mi++)
                #pragma unroll
                for (int ni = 0; ni < 4; ni++)
                    mma_tf32(c[mi][ni], af[mi], bf[ni]);
        }
        __syncthreads();
    }

    // epilogue: c0,c1 at (g, 2*t4 / +1); c2,c3 at (g+8, same cols)
    #pragma unroll
    for (int mi = 0; mi < 4; mi++) {
        int row0 = bm + wm * 64 + mi * 16 + g;
        #pragma unroll
        for (int ni = 0; ni < 4; ni++) {
            int col = bn + wn * 32 + ni * 8 + t4 * 2;
            if (row0 < M)
                *reinterpret_cast<float2*>(Cm + (size_t)row0 * N + col) =
                    make_float2(c[mi][ni][0], c[mi][ni][1]);
            if (row0 + 8 < M)
                *reinterpret_cast<float2*>(Cm + (size_t)(row0 + 8) * N + col) =
                    make_float2(c[mi][ni][2], c[mi][ni][3]);
        }
    }
}

// ---- attention coefficients: s_n, d_n  (one warp per (node, head)) ---------

__global__ void compute_sd(const float* __restrict__ h,
                           const float* __restrict__ a_src,
                           const float* __restrict__ a_dst,
                           float* __restrict__ sn, float* __restrict__ dn,
                           int N, int H, int C) {
    int w = (blockIdx.x * blockDim.x + threadIdx.x) >> 5;
    int lane = threadIdx.x & 31;
    if (w >= N * H) return;
    int n = w / H, hh = w % H;
    const float* row = h + (size_t)n * H * C + hh * C;
    const float* as = a_src + hh * C;
    const float* ad = a_dst + hh * C;
    float s = 0.f, d = 0.f;
    for (int c = lane; c < C; c += 32) {
        float v = row[c];
        s += v * as[c];
        d += v * ad[c];
    }
    #pragma unroll
    for (int o = 16; o; o >>= 1) {
        s += __shfl_down_sync(0xffffffffu, s, o);
        d += __shfl_down_sync(0xffffffffu, d, o);
    }
    if (lane == 0) { sn[w] = s; dn[w] = d; }
}

// ---- edge pass 1: e = leaky_relu(s[src]+d[dst]); segment max ---------------

template <int H>
__global__ void edge_pass1(const int* __restrict__ ei,
                           const float* __restrict__ sn,
                           const float* __restrict__ dn,
                           float* __restrict__ ebuf,
                           unsigned* __restrict__ menc, int E, int N) {
    int eid = blockIdx.x * blockDim.x + threadIdx.x;
    if (eid >= E + N) return;
    int src, dst;
    if (eid < E) { src = ei[eid]; dst = ei[E + eid]; }
    else         { src = dst = eid - E; }
    #pragma unroll
    for (int h = 0; h < H; h++) {
        float e = sn[src * H + h] + dn[dst * H + h];
        e = e > 0.f ? e : 0.2f * e;
        ebuf[eid * H + h] = e;
        atomicMax(&menc[dst * H + h], fenc(e));
    }
}

// ---- edge pass 2: ex = exp(e - m[dst]); segment sum ------------------------

template <int H>
__global__ void edge_pass2(const int* __restrict__ ei,
                           float* __restrict__ ebuf,
                           const unsigned* __restrict__ menc,
                           float* __restrict__ den, int E, int N) {
    int eid = blockIdx.x * blockDim.x + threadIdx.x;
    if (eid >= E + N) return;
    int dst;
    if (eid < E) dst = ei[E + eid];
    else         dst = eid - E;
    #pragma unroll
    for (int h = 0; h < H; h++) {
        float m = fdec(menc[dst * H + h]);
        float ex = __expf(ebuf[eid * H + h] - m);
        ebuf[eid * H + h] = ex;
        atomicAdd(&den[dst * H + h], ex);
    }
}

// ---- edge pass 3: out[dst] += alpha * h[src]  (float4 reductions) ----------

template <int H, int C>
__global__ void edge_pass3(const int* __restrict__ ei,
                           const float4* __restrict__ hf,
                           const float* __restrict__ ebuf,
                           const float* __restrict__ den,
                           float4* __restrict__ outp, int E, int N, int tot) {
    constexpr int J = H * C / 4;
    int t = blockIdx.x * blockDim.x + threadIdx.x;
    if (t >= tot) return;
    int eid = t / J, j = t % J;
    int src, dst;
    if (eid < E) { src = ei[eid]; dst = ei[E + eid]; }
    else         { src = dst = eid - E; }
    int h = (j * 4) / C;
    float alpha = ebuf[eid * H + h] / (den[dst * H + h] + 1e-16f);
    float4 v = __ldg(hf + (size_t)src * J + j);
    v.x *= alpha; v.y *= alpha; v.z *= alpha; v.w *= alpha;
    red_add_v4(reinterpret_cast<float*>(outp + (size_t)dst * J + j), v);
}

// ---- epilogue: bias + optional ELU ----------------------------------------

__global__ void bias_act(const float* __restrict__ in, const float* __restrict__ b,
                         float* __restrict__ out, int total, int D, int act) {
    int t = blockIdx.x * blockDim.x + threadIdx.x;
    if (t >= total) return;
    float v = in[t] + b[t % D];
    if (act) v = v > 0.f ? v : (__expf(v) - 1.f);
    out[t] = v;
}

// ---- MLP head --------------------------------------------------------------

__global__ __launch_bounds__(64)
void head_kernel(const float* __restrict__ emb, const float* __restrict__ Wh1,
                 const float* __restrict__ bh1, const float* __restrict__ Wh2,
                 const float* __restrict__ bh2, float* __restrict__ scores, int N) {
    int n = blockIdx.x;
    int j = threadIdx.x;  // 64 threads
    __shared__ float er[128];
    __shared__ float zs[64];
    er[j]      = emb[(size_t)n * 128 + j];
    er[j + 64] = emb[(size_t)n * 128 + 64 + j];
    __syncthreads();
    const float* w = Wh1 + j * 128;
    float s = 0.f;
    #pragma unroll 8
    for (int k = 0; k < 128; k++) s += er[k] * w[k];
    s += bh1[j];
    s = fmaxf(s, 0.f);
    zs[j] = s * Wh2[j];
    __syncthreads();
    if (j < 32) {
        float v = zs[j] + zs[j + 32];
        #pragma unroll
        for (int o = 16; o; o >>= 1) v += __shfl_down_sync(0xffffffffu, v, o);
        if (j == 0) scores[n] = 1.f / (1.f + __expf(-(v + bh2[0])));
    }
}

// ---------------------------------------------------------------------------

extern "C" void kernel_launch(void* const* d_in, const int* in_sizes, int n_in,
                              void* d_out, int out_size) {
    const float* x  = (const float*)d_in[0];
    const int*   ei = (const int*)d_in[1];   // int32 (JAX x64 disabled)
    const float *W1 = (const float*)d_in[2],  *as1 = (const float*)d_in[3],
                *ad1 = (const float*)d_in[4], *b1 = (const float*)d_in[5];
    const float *W2 = (const float*)d_in[6],  *as2 = (const float*)d_in[7],
                *ad2 = (const float*)d_in[8], *b2 = (const float*)d_in[9];
    const float *W3 = (const float*)d_in[10], *as3 = (const float*)d_in[11],
                *ad3 = (const float*)d_in[12], *b3 = (const float*)d_in[13];
    const float *Wh1 = (const float*)d_in[14], *bh1 = (const float*)d_in[15],
                *Wh2 = (const float*)d_in[16], *bh2 = (const float*)d_in[17];
    float* out = (float*)d_out;

    const int N = in_sizes[0] / 256;
    const int E = in_sizes[1] / 2;
    const int ET = E + N;

    float4 *gh4, *gout4, *ebuf4;
    float *snp, *dnp, *den;
    unsigned* menc;
    cudaGetSymbolAddress((void**)&gh4,   g_h_buf4);
    cudaGetSymbolAddress((void**)&gout4, g_out_buf4);
    cudaGetSymbolAddress((void**)&snp,   g_sn_buf);
    cudaGetSymbolAddress((void**)&dnp,   g_dn_buf);
    cudaGetSymbolAddress((void**)&menc,  g_m_buf);
    cudaGetSymbolAddress((void**)&den,   g_den_buf);
    cudaGetSymbolAddress((void**)&ebuf4, g_e_buf4);
    float* gh   = (float*)gh4;
    float* gout = (float*)gout4;
    float* ebuf = (float*)ebuf4;

    auto cdiv = [](int a, int b) { return (a + b - 1) / b; };

    auto run_layer = [&](const float* fin, int Fin, const float* W,
                         const float* as, const float* ad, const float* bb,
                         int H, int C, int act, float* finalout) {
        const int HC = H * C;
        // 1) transform on tensor cores (runs before gout is re-zeroed)
        dim3 gg(cdiv(HC, 128), cdiv(N, 128));
        sgemm_tf32<<<gg, 256>>>(fin, W, gh, N, HC, Fin);
        // 2) init segment buffers + output accumulator
        int nh = N * H;
        fill_u32<<<cdiv(nh, 256), 256>>>(menc, 0u, nh);
        fill_f32<<<cdiv(nh, 256), 256>>>(den, 0.f, nh);
        fill_f32<<<cdiv(N * HC, 256), 256>>>(gout, 0.f, N * HC);
        // 3) per-node attention coefficients
        compute_sd<<<cdiv(nh * 32, 256), 256>>>(gh, as, ad, snp, dnp, N, H, C);
        // 4-6) edge passes
        if (H == 4) {
            edge_pass1<4><<<cdiv(ET, 256), 256>>>(ei, snp, dnp, ebuf, menc, E, N);
            edge_pass2<4><<<cdiv(ET, 256), 256>>>(ei, ebuf, menc, den, E, N);
            int tot = ET * (4 * 128 / 4);
            edge_pass3<4, 128><<<cdiv(tot, 256), 256>>>(ei, gh4, ebuf, den, gout4, E, N, tot);
        } else {
            edge_pass1<1><<<cdiv(ET, 256), 256>>>(ei, snp, dnp, ebuf, menc, E, N);
            edge_pass2<1><<<cdiv(ET, 256), 256>>>(ei, ebuf, menc, den, E, N);
            int tot = ET * (1 * 128 / 4);
            edge_pass3<1, 128><<<cdiv(tot, 256), 256>>>(ei, gh4, ebuf, den, gout4, E, N, tot);
        }
        // 7) bias + activation
        bias_act<<<cdiv(N * HC, 256), 256>>>(gout, bb, finalout, N * HC, HC, act);
    };

    // layer 1: 256 -> 4x128 concat, ELU
    run_layer(x, 256, W1, as1, ad1, b1, 4, 128, 1, gout);
    // layer 2: 512 -> 4x128 concat, ELU
    run_layer(gout, 512, W2, as2, ad2, b2, 4, 128, 1, gout);
    // layer 3: 512 -> 1x128, embeddings straight into d_out
    run_layer(gout, 512, W3, as3, ad3, b3, 1, 128, 0, out);

    // MLP head -> scores at d_out[N*128 ..)
    head_kernel<<<N, 64>>>(out, Wh1, bh1, Wh2, bh2, out + (size_t)N * 128, N);
}

// round 10
// speedup vs baseline: 1.3228x; 1.1058x over previous
#include <cuda_runtime.h>
#include <cstdint>

// ---------------------------------------------------------------------------
// AllocationGNN: 3x GATConv + MLP head.  R10:
//  - GEMM: register-staged global prefetch (overlap LDG with mma)
//  - softmax: max-pass eliminated (identity), pass1+2 merged
//  - inv_den precomputed (kills 109M divides in pass3)
//  - pass3: warp-per-edge, coalesced float4 gather/RED
//  - float4 bias_act, memset fills
// ---------------------------------------------------------------------------

#define NMAX 50000
#define EMAX 800000
#define ETMAX (EMAX + NMAX)

__device__ float4   g_h_buf4[(size_t)NMAX * 128];    // N*512 floats
__device__ float4   g_out_buf4[(size_t)NMAX * 128];  // N*512 floats
__device__ float    g_sn_buf[NMAX * 4];
__device__ float    g_dn_buf[NMAX * 4];
__device__ float    g_inv_buf[NMAX * 4];
__device__ float    g_den_buf[NMAX * 4];
__device__ float4   g_e_buf4[(size_t)ETMAX];         // ET*4 floats

// ---- helpers ---------------------------------------------------------------

__device__ __forceinline__ void red_add_v4(float* p, float4 v) {
    asm volatile("red.global.add.v4.f32 [%0], {%1,%2,%3,%4};"
                 :: "l"(p), "f"(v.x), "f"(v.y), "f"(v.z), "f"(v.w)
                 : "memory");
}
__device__ __forceinline__ uint32_t f2tf32(float f) {
    uint32_t r;
    asm("cvt.rna.tf32.f32 %0, %1;" : "=r"(r) : "f"(f));
    return r;
}
__device__ __forceinline__ void mma_tf32(float* c, const uint32_t* a,
                                         const uint32_t* b) {
    asm volatile(
        "mma.sync.aligned.m16n8k8.row.col.f32.tf32.tf32.f32 "
        "{%0,%1,%2,%3}, {%4,%5,%6,%7}, {%8,%9}, {%0,%1,%2,%3};"
        : "+f"(c[0]), "+f"(c[1]), "+f"(c[2]), "+f"(c[3])
        : "r"(a[0]), "r"(a[1]), "r"(a[2]), "r"(a[3]), "r"(b[0]), "r"(b[1]));
}

// ---- TF32 tensor-core GEMM with register-staged prefetch -------------------
// C[M,N] = A[M,K] * B[N,K]^T.  Block 128x128x16, 8 warps (2x4), warp 64x32.
// Requires K%16==0, N%128==0.

__global__ __launch_bounds__(256, 2)
void sgemm_tf32(const float* __restrict__ A, const float* __restrict__ B,
                float* __restrict__ Cm, int M, int N, int K) {
    constexpr int BM = 128, BN = 128, BK = 16, LDS = BK + 4;
    __shared__ uint32_t As[BM][LDS];
    __shared__ uint32_t Bs[BN][LDS];
    const int tid  = threadIdx.x;
    const int warp = tid >> 5, lane = tid & 31;
    const int wm = warp >> 2, wn = warp & 3;
    const int g = lane >> 2, t4 = lane & 3;
    const int bm = blockIdx.y * BM, bn = blockIdx.x * BN;

    float c[4][4][4];
    #pragma unroll
    for (int mi = 0; mi < 4; mi++)
        #pragma unroll
        for (int ni = 0; ni < 4; ni++)
            #pragma unroll
            for (int q = 0; q < 4; q++) c[mi][ni][q] = 0.f;

    float4 pva[2], pvb[2];
    const int r0  = tid >> 2;
    const int c40 = (tid & 3) << 2;
    const int r1  = (tid + 256) >> 2;
    // (c4 for second chunk equals c40: (tid+256)&3 == tid&3)

    auto ldtile = [&](int k0) {
        pva[0] = (bm + r0 < M)
            ? *reinterpret_cast<const float4*>(A + (size_t)(bm + r0) * K + k0 + c40)
            : make_float4(0.f, 0.f, 0.f, 0.f);
        pvb[0] = *reinterpret_cast<const float4*>(B + (size_t)(bn + r0) * K + k0 + c40);
        pva[1] = (bm + r1 < M)
            ? *reinterpret_cast<const float4*>(A + (size_t)(bm + r1) * K + k0 + c40)
            : make_float4(0.f, 0.f, 0.f, 0.f);
        pvb[1] = *reinterpret_cast<const float4*>(B + (size_t)(bn + r1) * K + k0 + c40);
    };
    auto sttile = [&]() {
        #pragma unroll
        for (int i = 0; i < 2; i++) {
            int r = i ? r1 : r0;
            As[r][c40 + 0] = f2tf32(pva[i].x); As[r][c40 + 1] = f2tf32(pva[i].y);
            As[r][c40 + 2] = f2tf32(pva[i].z); As[r][c40 + 3] = f2tf32(pva[i].w);
            Bs[r][c40 + 0] = f2tf32(pvb[i].x); Bs[r][c40 + 1] = f2tf32(pvb[i].y);
            Bs[r][c40 + 2] = f2tf32(pvb[i].z); Bs[r][c40 + 3] = f2tf32(pvb[i].w);
        }
    };

    ldtile(0);
    sttile();
    __syncthreads();

    for (int k0 = 0; k0 < K; k0 += BK) {
        const bool more = (k0 + BK) < K;
        if (more) ldtile(k0 + BK);   // LDGs in flight during mma below

        #pragma unroll
        for (int ks = 0; ks < BK; ks += 8) {
            uint32_t af[4][4], bf[4][2];
            #pragma unroll
            for (int mi = 0; mi < 4; mi++) {
                int row = wm * 64 + mi * 16;
                af[mi][0] = As[row + g][ks + t4];
                af[mi][1] = As[row + g + 8][ks + t4];
                af[mi][2] = As[row + g][ks + t4 + 4];
                af[mi][3] = As[row + g + 8][ks + t4 + 4];
            }
            #pragma unroll
            for (int ni = 0; ni < 4; ni++) {
                int col = wn * 32 + ni * 8;
                bf[ni][0] = Bs[col + g][ks + t4];
                bf[ni][1] = Bs[col + g][ks + t4 + 4];
            }
            #pragma unroll
            for (int mi = 0; mi < 4; mi++)
                #pragma unroll
                for (int ni = 0; ni < 4; ni++)
                    mma_tf32(c[mi][ni], af[mi], bf[ni]);
        }

        if (more) {
            __syncthreads();
            sttile();
            __syncthreads();
        }
    }

    #pragma unroll
    for (int mi = 0; mi < 4; mi++) {
        int row0 = bm + wm * 64 + mi * 16 + g;
        #pragma unroll
        for (int ni = 0; ni < 4; ni++) {
            int col = bn + wn * 32 + ni * 8 + t4 * 2;
            if (row0 < M)
                *reinterpret_cast<float2*>(Cm + (size_t)row0 * N + col) =
                    make_float2(c[mi][ni][0], c[mi][ni][1]);
            if (row0 + 8 < M)
                *reinterpret_cast<float2*>(Cm + (size_t)(row0 + 8) * N + col) =
                    make_float2(c[mi][ni][2], c[mi][ni][3]);
        }
    }
}

// ---- attention coefficients: s_n, d_n (warp per (node,head), float4) -------

__global__ void compute_sd(const float4* __restrict__ h,
                           const float4* __restrict__ a_src,
                           const float4* __restrict__ a_dst,
                           float* __restrict__ sn, float* __restrict__ dn,
                           int N, int H) {
    int w = (blockIdx.x * blockDim.x + threadIdx.x) >> 5;
    int lane = threadIdx.x & 31;
    if (w >= N * H) return;
    int n = w / H, hh = w - n * H;
    // C=128 floats = 32 float4; one float4 per lane
    float4 v  = h[(size_t)n * H * 32 + hh * 32 + lane];
    float4 as = a_src[hh * 32 + lane];
    float4 ad = a_dst[hh * 32 + lane];
    float s = v.x * as.x + v.y * as.y + v.z * as.z + v.w * as.w;
    float d = v.x * ad.x + v.y * ad.y + v.z * ad.z + v.w * ad.w;
    #pragma unroll
    for (int o = 16; o; o >>= 1) {
        s += __shfl_down_sync(0xffffffffu, s, o);
        d += __shfl_down_sync(0xffffffffu, d, o);
    }
    if (lane == 0) { sn[w] = s; dn[w] = d; }
}

// ---- merged edge pass: ex = exp(leaky(s[src]+d[dst])); segment sum ---------

template <int H>
__global__ void edge_pass12(const int* __restrict__ ei,
                            const float* __restrict__ sn,
                            const float* __restrict__ dn,
                            float* __restrict__ ebuf,
                            float* __restrict__ den, int E, int N) {
    int eid = blockIdx.x * blockDim.x + threadIdx.x;
    if (eid >= E + N) return;
    int src, dst;
    if (eid < E) { src = ei[eid]; dst = ei[E + eid]; }
    else         { src = dst = eid - E; }
    #pragma unroll
    for (int h = 0; h < H; h++) {
        float e = sn[src * H + h] + dn[dst * H + h];
        e = e > 0.f ? e : 0.2f * e;
        float ex = __expf(e);
        ebuf[eid * H + h] = ex;
        atomicAdd(&den[dst * H + h], ex);
    }
}

// ---- inv_den ---------------------------------------------------------------

__global__ void inv_den_k(const float* __restrict__ den,
                          float* __restrict__ inv, int n) {
    int i = blockIdx.x * blockDim.x + threadIdx.x;
    if (i < n) inv[i] = 1.f / (den[i] + 1e-16f);
}

// ---- edge pass 3: warp per edge; out[dst] += alpha * h[src] ---------------

template <int H, int C>
__global__ void edge_pass3(const int* __restrict__ ei,
                           const float4* __restrict__ hf,
                           const float* __restrict__ ebuf,
                           const float* __restrict__ inv,
                           float4* __restrict__ outp, int E, int N) {
    constexpr int J = H * C / 4;              // float4 chunks per node row
    constexpr int PER = J / 32;               // chunks per lane (4 or 1)
    int w = (blockIdx.x * blockDim.x + threadIdx.x) >> 5;
    int lane = threadIdx.x & 31;
    if (w >= E + N) return;
    int src, dst;
    if (w < E) { src = __ldg(ei + w); dst = __ldg(ei + E + w); }
    else       { src = dst = w - E; }
    // lane l covers chunks [l*PER, l*PER+PER): head = const per lane
    int head = (H == 1) ? 0 : (lane >> 3);
    float alpha = ebuf[w * H + head] * inv[dst * H + head];
    const float4* hrow = hf + (size_t)src * J + lane * PER;
    float4* orow = outp + (size_t)dst * J + lane * PER;
    #pragma unroll
    for (int it = 0; it < PER; it++) {
        float4 v = __ldg(hrow + it);
        v.x *= alpha; v.y *= alpha; v.z *= alpha; v.w *= alpha;
        red_add_v4(reinterpret_cast<float*>(orow + it), v);
    }
}

// ---- epilogue: bias + optional ELU (float4) --------------------------------

__global__ void bias_act4(const float4* __restrict__ in,
                          const float4* __restrict__ b,
                          float4* __restrict__ out, int total4,
                          int dmask, int act) {
    int t = blockIdx.x * blockDim.x + threadIdx.x;
    if (t >= total4) return;
    float4 v = in[t];
    float4 bb = b[t & dmask];
    v.x += bb.x; v.y += bb.y; v.z += bb.z; v.w += bb.w;
    if (act) {
        v.x = v.x > 0.f ? v.x : (__expf(v.x) - 1.f);
        v.y = v.y > 0.f ? v.y : (__expf(v.y) - 1.f);
        v.z = v.z > 0.f ? v.z : (__expf(v.z) - 1.f);
        v.w = v.w > 0.f ? v.w : (__expf(v.w) - 1.f);
    }
    out[t] = v;
}

// ---- MLP head --------------------------------------------------------------

__global__ __launch_bounds__(64)
void head_kernel(const float* __restrict__ emb, const float* __restrict__ Wh1,
                 const float* __restrict__ bh1, const float* __restrict__ Wh2,
                 const float* __restrict__ bh2, float* __restrict__ scores, int N) {
    int n = blockIdx.x;
    int j = threadIdx.x;
    __shared__ float er[128];
    __shared__ float zs[64];
    er[j]      = emb[(size_t)n * 128 + j];
    er[j + 64] = emb[(size_t)n * 128 + 64 + j];
    __syncthreads();
    const float* w = Wh1 + j * 128;
    float s = 0.f;
    #pragma unroll 8
    for (int k = 0; k < 128; k++) s += er[k] * w[k];
    s += bh1[j];
    s = fmaxf(s, 0.f);
    zs[j] = s * Wh2[j];
    __syncthreads();
    if (j < 32) {
        float v = zs[j] + zs[j + 32];
        #pragma unroll
        for (int o = 16; o; o >>= 1) v += __shfl_down_sync(0xffffffffu, v, o);
        if (j == 0) scores[n] = 1.f / (1.f + __expf(-(v + bh2[0])));
    }
}

// ---------------------------------------------------------------------------

extern "C" void kernel_launch(void* const* d_in, const int* in_sizes, int n_in,
                              void* d_out, int out_size) {
    const float* x  = (const float*)d_in[0];
    const int*   ei = (const int*)d_in[1];
    const float *W1 = (const float*)d_in[2],  *as1 = (const float*)d_in[3],
                *ad1 = (const float*)d_in[4], *b1 = (const float*)d_in[5];
    const float *W2 = (const float*)d_in[6],  *as2 = (const float*)d_in[7],
                *ad2 = (const float*)d_in[8], *b2 = (const float*)d_in[9];
    const float *W3 = (const float*)d_in[10], *as3 = (const float*)d_in[11],
                *ad3 = (const float*)d_in[12], *b3 = (const float*)d_in[13];
    const float *Wh1 = (const float*)d_in[14], *bh1 = (const float*)d_in[15],
                *Wh2 = (const float*)d_in[16], *bh2 = (const float*)d_in[17];
    float* out = (float*)d_out;

    const int N = in_sizes[0] / 256;
    const int E = in_sizes[1] / 2;
    const int ET = E + N;

    float4 *gh4, *gout4, *ebuf4;
    float *snp, *dnp, *den, *inv;
    cudaGetSymbolAddress((void**)&gh4,   g_h_buf4);
    cudaGetSymbolAddress((void**)&gout4, g_out_buf4);
    cudaGetSymbolAddress((void**)&snp,   g_sn_buf);
    cudaGetSymbolAddress((void**)&dnp,   g_dn_buf);
    cudaGetSymbolAddress((void**)&inv,   g_inv_buf);
    cudaGetSymbolAddress((void**)&den,   g_den_buf);
    cudaGetSymbolAddress((void**)&ebuf4, g_e_buf4);
    float* gh   = (float*)gh4;
    float* gout = (float*)gout4;
    float* ebuf = (float*)ebuf4;

    auto cdiv = [](int a, int b) { return (a + b - 1) / b; };

    auto run_layer = [&](const float* fin, int Fin, const float* W,
                         const float* as, const float* ad, const float* bb,
                         int H, int C, int act, float* finalout) {
        const int HC = H * C;
        // 1) transform on tensor cores (before gout is re-zeroed)
        dim3 gg(cdiv(HC, 128), cdiv(N, 128));
        sgemm_tf32<<<gg, 256>>>(fin, W, gh, N, HC, Fin);
        // 2) zero accumulators
        int nh = N * H;
        cudaMemsetAsync(den, 0, (size_t)nh * 4);
        cudaMemsetAsync(gout, 0, (size_t)N * HC * 4);
        // 3) attention coefficients
        compute_sd<<<cdiv(nh * 32, 256), 256>>>(
            (const float4*)gh, (const float4*)as, (const float4*)ad,
            snp, dnp, N, H);
        // 4) merged exp+sum pass, then reciprocal
        if (H == 4) {
            edge_pass12<4><<<cdiv(ET, 256), 256>>>(ei, snp, dnp, ebuf, den, E, N);
            inv_den_k<<<cdiv(nh, 256), 256>>>(den, inv, nh);
            edge_pass3<4, 128><<<cdiv(ET * 32, 256), 256>>>(ei, gh4, ebuf, inv, gout4, E, N);
        } else {
            edge_pass12<1><<<cdiv(ET, 256), 256>>>(ei, snp, dnp, ebuf, den, E, N);
            inv_den_k<<<cdiv(nh, 256), 256>>>(den, inv, nh);
            edge_pass3<1, 128><<<cdiv(ET * 32, 256), 256>>>(ei, gh4, ebuf, inv, gout4, E, N);
        }
        // 5) bias + activation
        int total4 = N * HC / 4;
        bias_act4<<<cdiv(total4, 256), 256>>>(
            (const float4*)gout, (const float4*)bb, (float4*)finalout,
            total4, HC / 4 - 1, act);
    };

    run_layer(x, 256, W1, as1, ad1, b1, 4, 128, 1, gout);
    run_layer(gout, 512, W2, as2, ad2, b2, 4, 128, 1, gout);
    run_layer(gout, 512, W3, as3, ad3, b3, 1, 128, 0, out);

    head_kernel<<<N, 64>>>(out, Wh1, bh1, Wh2, bh2, out + (size_t)N * 128, N);
}

// round 11
// speedup vs baseline: 1.8899x; 1.4287x over previous
#include <cuda_runtime.h>
#include <cstdint>

// ---------------------------------------------------------------------------
// AllocationGNN: 3x GATConv + MLP head.  R11:
//  - CSR (by destination) built once per call; aggregation is gather-side:
//    warp-per-node register accumulation, ZERO atomics in the hot path,
//    softmax denom + bias + ELU fused into the aggregate epilogue.
//  - GEMM: double-buffered smem (1 sync/iter) + register-staged prefetch.
// ---------------------------------------------------------------------------

#define NMAX 50000
#define EMAX 800000
#define ETMAX (EMAX + NMAX)

__device__ float4 g_h_buf4[(size_t)NMAX * 128];    // N*512 floats (GEMM out)
__device__ float4 g_out_buf4[(size_t)NMAX * 128];  // N*512 floats (layer out)
__device__ float  g_sn_buf[NMAX * 4];
__device__ float  g_dn_buf[NMAX * 4];
__device__ int    g_cnt[NMAX];
__device__ int    g_rp[NMAX + 1];
__device__ int    g_cursor[NMAX];
__device__ int    g_ssrc[ETMAX];
__device__ int    g_bsum[1024];

// ---- helpers ---------------------------------------------------------------

__device__ __forceinline__ uint32_t f2tf32(float f) {
    uint32_t r;
    asm("cvt.rna.tf32.f32 %0, %1;" : "=r"(r) : "f"(f));
    return r;
}
__device__ __forceinline__ void mma_tf32(float* c, const uint32_t* a,
                                         const uint32_t* b) {
    asm volatile(
        "mma.sync.aligned.m16n8k8.row.col.f32.tf32.tf32.f32 "
        "{%0,%1,%2,%3}, {%4,%5,%6,%7}, {%8,%9}, {%0,%1,%2,%3};"
        : "+f"(c[0]), "+f"(c[1]), "+f"(c[2]), "+f"(c[3])
        : "r"(a[0]), "r"(a[1]), "r"(a[2]), "r"(a[3]), "r"(b[0]), "r"(b[1]));
}

// ---- CSR build -------------------------------------------------------------

__global__ void hist_k(const int* __restrict__ ei, int* __restrict__ cnt,
                       int E, int N) {
    int i = blockIdx.x * blockDim.x + threadIdx.x;
    if (i >= E + N) return;
    int dst = (i < E) ? ei[E + i] : (i - E);
    atomicAdd(&cnt[dst], 1);
}

__global__ void scan1(const int* __restrict__ cnt, int* __restrict__ rp,
                      int* __restrict__ bsum, int N) {
    __shared__ int sh[1024];
    int tid = threadIdx.x, gid = blockIdx.x * 1024 + tid;
    int v = (gid < N) ? cnt[gid] : 0;
    sh[tid] = v;
    __syncthreads();
    for (int off = 1; off < 1024; off <<= 1) {
        int t = (tid >= off) ? sh[tid - off] : 0;
        __syncthreads();
        sh[tid] += t;
        __syncthreads();
    }
    if (gid < N) rp[gid] = sh[tid] - v;           // block-local exclusive
    if (tid == 1023) bsum[blockIdx.x] = sh[1023]; // block total
}

__global__ void scan2(int* __restrict__ bsum, int nb) {
    __shared__ int sh[1024];
    int tid = threadIdx.x;
    int v = (tid < nb) ? bsum[tid] : 0;
    sh[tid] = v;
    __syncthreads();
    for (int off = 1; off < 1024; off <<= 1) {
        int t = (tid >= off) ? sh[tid - off] : 0;
        __syncthreads();
        sh[tid] += t;
        __syncthreads();
    }
    if (tid < nb) bsum[tid] = sh[tid] - v;        // exclusive
}

__global__ void scan3(int* __restrict__ rp, const int* __restrict__ bsum,
                      int* __restrict__ cursor, int N, int ET) {
    int gid = blockIdx.x * blockDim.x + threadIdx.x;
    if (gid < N) {
        int r = rp[gid] + bsum[gid >> 10];
        rp[gid] = r;
        cursor[gid] = r;
    }
    if (gid == N) rp[N] = ET;
}

__global__ void scatter_k(const int* __restrict__ ei, int* __restrict__ cursor,
                          int* __restrict__ ssrc, int E, int N) {
    int i = blockIdx.x * blockDim.x + threadIdx.x;
    if (i >= E + N) return;
    int src, dst;
    if (i < E) { src = ei[i]; dst = ei[E + i]; }
    else       { src = dst = i - E; }
    int p = atomicAdd(&cursor[dst], 1);
    ssrc[p] = src;
}

// ---- TF32 GEMM: C[M,N] = A[M,K]*B[N,K]^T; double-buffered smem -------------

__global__ __launch_bounds__(256, 2)
void sgemm_tf32(const float* __restrict__ A, const float* __restrict__ B,
                float* __restrict__ Cm, int M, int N, int K) {
    constexpr int BM = 128, BN = 128, BK = 16, LDS = BK + 4;
    __shared__ uint32_t As[2][BM][LDS];
    __shared__ uint32_t Bs[2][BN][LDS];
    const int tid  = threadIdx.x;
    const int warp = tid >> 5, lane = tid & 31;
    const int wm = warp >> 2, wn = warp & 3;
    const int g = lane >> 2, t4 = lane & 3;
    const int bm = blockIdx.y * BM, bn = blockIdx.x * BN;

    float c[4][4][4];
    #pragma unroll
    for (int mi = 0; mi < 4; mi++)
        #pragma unroll
        for (int ni = 0; ni < 4; ni++)
            #pragma unroll
            for (int q = 0; q < 4; q++) c[mi][ni][q] = 0.f;

    float4 pva[2], pvb[2];
    const int r0  = tid >> 2;
    const int c40 = (tid & 3) << 2;
    const int r1  = (tid + 256) >> 2;

    auto ldtile = [&](int k0) {
        pva[0] = (bm + r0 < M)
            ? *reinterpret_cast<const float4*>(A + (size_t)(bm + r0) * K + k0 + c40)
            : make_float4(0.f, 0.f, 0.f, 0.f);
        pvb[0] = *reinterpret_cast<const float4*>(B + (size_t)(bn + r0) * K + k0 + c40);
        pva[1] = (bm + r1 < M)
            ? *reinterpret_cast<const float4*>(A + (size_t)(bm + r1) * K + k0 + c40)
            : make_float4(0.f, 0.f, 0.f, 0.f);
        pvb[1] = *reinterpret_cast<const float4*>(B + (size_t)(bn + r1) * K + k0 + c40);
    };
    auto sttile = [&](int s) {
        #pragma unroll
        for (int i = 0; i < 2; i++) {
            int r = i ? r1 : r0;
            As[s][r][c40 + 0] = f2tf32(pva[i].x); As[s][r][c40 + 1] = f2tf32(pva[i].y);
            As[s][r][c40 + 2] = f2tf32(pva[i].z); As[s][r][c40 + 3] = f2tf32(pva[i].w);
            Bs[s][r][c40 + 0] = f2tf32(pvb[i].x); Bs[s][r][c40 + 1] = f2tf32(pvb[i].y);
            Bs[s][r][c40 + 2] = f2tf32(pvb[i].z); Bs[s][r][c40 + 3] = f2tf32(pvb[i].w);
        }
    };

    ldtile(0);
    sttile(0);
    __syncthreads();
    int st = 0;

    for (int k0 = 0; k0 < K; k0 += BK) {
        const bool more = (k0 + BK) < K;
        if (more) ldtile(k0 + BK);   // LDGs in flight during mma

        #pragma unroll
        for (int ks = 0; ks < BK; ks += 8) {
            uint32_t af[4][4], bf[4][2];
            #pragma unroll
            for (int mi = 0; mi < 4; mi++) {
                int row = wm * 64 + mi * 16;
                af[mi][0] = As[st][row + g][ks + t4];
                af[mi][1] = As[st][row + g + 8][ks + t4];
                af[mi][2] = As[st][row + g][ks + t4 + 4];
                af[mi][3] = As[st][row + g + 8][ks + t4 + 4];
            }
            #pragma unroll
            for (int ni = 0; ni < 4; ni++) {
                int col = wn * 32 + ni * 8;
                bf[ni][0] = Bs[st][col + g][ks + t4];
                bf[ni][1] = Bs[st][col + g][ks + t4 + 4];
            }
            #pragma unroll
            for (int mi = 0; mi < 4; mi++)
                #pragma unroll
                for (int ni = 0; ni < 4; ni++)
                    mma_tf32(c[mi][ni], af[mi], bf[ni]);
        }

        if (more) {
            sttile(st ^ 1);          // inactive buffer: no pre-sync needed
            st ^= 1;
            __syncthreads();
        }
    }

    #pragma unroll
    for (int mi = 0; mi < 4; mi++) {
        int row0 = bm + wm * 64 + mi * 16 + g;
        #pragma unroll
        for (int ni = 0; ni < 4; ni++) {
            int col = bn + wn * 32 + ni * 8 + t4 * 2;
            if (row0 < M)
                *reinterpret_cast<float2*>(Cm + (size_t)row0 * N + col) =
                    make_float2(c[mi][ni][0], c[mi][ni][1]);
            if (row0 + 8 < M)
                *reinterpret_cast<float2*>(Cm + (size_t)(row0 + 8) * N + col) =
                    make_float2(c[mi][ni][2], c[mi][ni][3]);
        }
    }
}

// ---- attention coefficients: s_n, d_n (warp per (node,head), float4) -------

__global__ void compute_sd(const float4* __restrict__ h,
                           const float4* __restrict__ a_src,
                           const float4* __restrict__ a_dst,
                           float* __restrict__ sn, float* __restrict__ dn,
                           int N, int H) {
    int w = (blockIdx.x * blockDim.x + threadIdx.x) >> 5;
    int lane = threadIdx.x & 31;
    if (w >= N * H) return;
    int n = w / H, hh = w - n * H;
    float4 v  = h[(size_t)n * H * 32 + hh * 32 + lane];
    float4 as = a_src[hh * 32 + lane];
    float4 ad = a_dst[hh * 32 + lane];
    float s = v.x * as.x + v.y * as.y + v.z * as.z + v.w * as.w;
    float d = v.x * ad.x + v.y * ad.y + v.z * ad.z + v.w * ad.w;
    #pragma unroll
    for (int o = 16; o; o >>= 1) {
        s += __shfl_down_sync(0xffffffffu, s, o);
        d += __shfl_down_sync(0xffffffffu, d, o);
    }
    if (lane == 0) { sn[w] = s; dn[w] = d; }
}

// ---- gather aggregation: warp per destination node -------------------------
// out[n] = elu?( bias + (1/den) * sum_{e in in(n)} ex_e * h[src_e] )
// ex_e = exp(leaky_relu(sn[src]+dn[n])), den = sum ex_e.  No atomics.

template <int H>
__global__ void aggregate_k(const int* __restrict__ rp,
                            const int* __restrict__ ssrc,
                            const float4* __restrict__ hf,
                            const float* __restrict__ sn,
                            const float* __restrict__ dn,
                            const float4* __restrict__ bias, int act,
                            float4* __restrict__ outp, int N) {
    constexpr int J = H * 32;      // float4 per node row
    constexpr int PER = J / 32;    // 4 for H=4, 1 for H=1
    int n = (blockIdx.x * blockDim.x + threadIdx.x) >> 5;
    int lane = threadIdx.x & 31;
    if (n >= N) return;
    const int head = (H == 1) ? 0 : (lane >> 3);

    // lanes < H own one head's coefficient math
    float dnv = (lane < H) ? dn[n * H + lane] : 0.f;

    float4 acc[PER];
    #pragma unroll
    for (int it = 0; it < PER; it++) acc[it] = make_float4(0.f, 0.f, 0.f, 0.f);
    float den = 0.f;

    const int s0 = rp[n], s1 = rp[n + 1];
    for (int p = s0; p < s1; p++) {
        int src = __ldg(ssrc + p);
        float exv = 0.f;
        if (lane < H) {
            float e = sn[src * H + lane] + dnv;
            e = e > 0.f ? e : 0.2f * e;
            exv = __expf(e);
        }
        float ex = __shfl_sync(0xffffffffu, exv, head);
        den += ex;
        const float4* hrow = hf + (size_t)src * J + lane * PER;
        #pragma unroll
        for (int it = 0; it < PER; it++) {
            float4 v = __ldg(hrow + it);
            acc[it].x += ex * v.x; acc[it].y += ex * v.y;
            acc[it].z += ex * v.z; acc[it].w += ex * v.w;
        }
    }

    float sc = 1.f / (den + 1e-16f);
    float4* orow = outp + (size_t)n * J + lane * PER;
    #pragma unroll
    for (int it = 0; it < PER; it++) {
        float4 bb = bias[lane * PER + it];
        float4 v;
        v.x = acc[it].x * sc + bb.x;
        v.y = acc[it].y * sc + bb.y;
        v.z = acc[it].z * sc + bb.z;
        v.w = acc[it].w * sc + bb.w;
        if (act) {
            v.x = v.x > 0.f ? v.x : (__expf(v.x) - 1.f);
            v.y = v.y > 0.f ? v.y : (__expf(v.y) - 1.f);
            v.z = v.z > 0.f ? v.z : (__expf(v.z) - 1.f);
            v.w = v.w > 0.f ? v.w : (__expf(v.w) - 1.f);
        }
        orow[it] = v;
    }
}

// ---- MLP head --------------------------------------------------------------

__global__ __launch_bounds__(64)
void head_kernel(const float* __restrict__ emb, const float* __restrict__ Wh1,
                 const float* __restrict__ bh1, const float* __restrict__ Wh2,
                 const float* __restrict__ bh2, float* __restrict__ scores, int N) {
    int n = blockIdx.x;
    int j = threadIdx.x;
    __shared__ float er[128];
    __shared__ float zs[64];
    er[j]      = emb[(size_t)n * 128 + j];
    er[j + 64] = emb[(size_t)n * 128 + 64 + j];
    __syncthreads();
    const float* w = Wh1 + j * 128;
    float s = 0.f;
    #pragma unroll 8
    for (int k = 0; k < 128; k++) s += er[k] * w[k];
    s += bh1[j];
    s = fmaxf(s, 0.f);
    zs[j] = s * Wh2[j];
    __syncthreads();
    if (j < 32) {
        float v = zs[j] + zs[j + 32];
        #pragma unroll
        for (int o = 16; o; o >>= 1) v += __shfl_down_sync(0xffffffffu, v, o);
        if (j == 0) scores[n] = 1.f / (1.f + __expf(-(v + bh2[0])));
    }
}

// ---------------------------------------------------------------------------

extern "C" void kernel_launch(void* const* d_in, const int* in_sizes, int n_in,
                              void* d_out, int out_size) {
    const float* x  = (const float*)d_in[0];
    const int*   ei = (const int*)d_in[1];
    const float *W1 = (const float*)d_in[2],  *as1 = (const float*)d_in[3],
                *ad1 = (const float*)d_in[4], *b1 = (const float*)d_in[5];
    const float *W2 = (const float*)d_in[6],  *as2 = (const float*)d_in[7],
                *ad2 = (const float*)d_in[8], *b2 = (const float*)d_in[9];
    const float *W3 = (const float*)d_in[10], *as3 = (const float*)d_in[11],
                *ad3 = (const float*)d_in[12], *b3 = (const float*)d_in[13];
    const float *Wh1 = (const float*)d_in[14], *bh1 = (const float*)d_in[15],
                *Wh2 = (const float*)d_in[16], *bh2 = (const float*)d_in[17];
    float* out = (float*)d_out;

    const int N = in_sizes[0] / 256;
    const int E = in_sizes[1] / 2;
    const int ET = E + N;

    float4 *gh4, *gout4;
    float *snp, *dnp;
    int *cnt, *rp, *cursor, *ssrc, *bsum;
    cudaGetSymbolAddress((void**)&gh4,    g_h_buf4);
    cudaGetSymbolAddress((void**)&gout4,  g_out_buf4);
    cudaGetSymbolAddress((void**)&snp,    g_sn_buf);
    cudaGetSymbolAddress((void**)&dnp,    g_dn_buf);
    cudaGetSymbolAddress((void**)&cnt,    g_cnt);
    cudaGetSymbolAddress((void**)&rp,     g_rp);
    cudaGetSymbolAddress((void**)&cursor, g_cursor);
    cudaGetSymbolAddress((void**)&ssrc,   g_ssrc);
    cudaGetSymbolAddress((void**)&bsum,   g_bsum);
    float* gh   = (float*)gh4;
    float* gout = (float*)gout4;

    auto cdiv = [](int a, int b) { return (a + b - 1) / b; };

    // ---- CSR build (once; reused by all 3 layers) ----
    const int nb = cdiv(N, 1024);
    cudaMemsetAsync(cnt, 0, (size_t)N * 4);
    hist_k<<<cdiv(ET, 256), 256>>>(ei, cnt, E, N);
    scan1<<<nb, 1024>>>(cnt, rp, bsum, N);
    scan2<<<1, 1024>>>(bsum, nb);
    scan3<<<cdiv(N + 1, 256), 256>>>(rp, bsum, cursor, N, ET);
    scatter_k<<<cdiv(ET, 256), 256>>>(ei, cursor, ssrc, E, N);

    // ---- generic GAT layer ----
    auto run_layer = [&](const float* fin, int Fin, const float* W,
                         const float* as, const float* ad, const float* bb,
                         int H, int act, float* finalout) {
        const int HC = H * 128;
        dim3 gg(cdiv(HC, 128), cdiv(N, 128));
        sgemm_tf32<<<gg, 256>>>(fin, W, gh, N, HC, Fin);
        compute_sd<<<cdiv(N * H * 32, 256), 256>>>(
            (const float4*)gh, (const float4*)as, (const float4*)ad,
            snp, dnp, N, H);
        if (H == 4)
            aggregate_k<4><<<cdiv(N * 32, 256), 256>>>(
                rp, ssrc, gh4, snp, dnp, (const float4*)bb, act,
                (float4*)finalout, N);
        else
            aggregate_k<1><<<cdiv(N * 32, 256), 256>>>(
                rp, ssrc, gh4, snp, dnp, (const float4*)bb, act,
                (float4*)finalout, N);
    };

    run_layer(x, 256, W1, as1, ad1, b1, 4, 1, gout);
    run_layer(gout, 512, W2, as2, ad2, b2, 4, 1, gout);
    run_layer(gout, 512, W3, as3, ad3, b3, 1, 0, out);

    head_kernel<<<N, 64>>>(out, Wh1, bh1, Wh2, bh2, out + (size_t)N * 128, N);
}

// round 12
// speedup vs baseline: 1.9068x; 1.0089x over previous
#include <cuda_runtime.h>
#include <cstdint>

// ---------------------------------------------------------------------------
// AllocationGNN: 3x GATConv + MLP head.  R12:
//  - tf32 rounding hoisted out of GEMM (pre-converted W & x; aggregate
//    epilogue rounds layer-1/2 outputs) -> GEMM hot loop is pure LDS+MMA
//  - GEMM: cp.async (LDGSTS) 3-stage pipeline, dynamic smem
//  - aggregation: unroll-2 edges for 2x memory-level parallelism
// ---------------------------------------------------------------------------

#define NMAX 50000
#define EMAX 800000
#define ETMAX (EMAX + NMAX)

__device__ float4 g_h_buf4[(size_t)NMAX * 128];    // N*512 floats (GEMM out)
__device__ float4 g_out_buf4[(size_t)NMAX * 128];  // N*512 floats (layer I/O)
__device__ float  g_sn_buf[NMAX * 4];
__device__ float  g_dn_buf[NMAX * 4];
__device__ float4 g_wc4[114688];                   // tf32-rounded W1|W2|W3
__device__ int    g_cnt[NMAX];
__device__ int    g_rp[NMAX + 1];
__device__ int    g_cursor[NMAX];
__device__ int    g_ssrc[ETMAX];
__device__ int    g_bsum[1024];

// ---- helpers ---------------------------------------------------------------

__device__ __forceinline__ uint32_t f2tf32(float f) {
    uint32_t r;
    asm("cvt.rna.tf32.f32 %0, %1;" : "=r"(r) : "f"(f));
    return r;
}
__device__ __forceinline__ float tf32r(float f) {
    return __uint_as_float(f2tf32(f));
}
__device__ __forceinline__ void mma_tf32(float* c, const uint32_t* a,
                                         const uint32_t* b) {
    asm volatile(
        "mma.sync.aligned.m16n8k8.row.col.f32.tf32.tf32.f32 "
        "{%0,%1,%2,%3}, {%4,%5,%6,%7}, {%8,%9}, {%0,%1,%2,%3};"
        : "+f"(c[0]), "+f"(c[1]), "+f"(c[2]), "+f"(c[3])
        : "r"(a[0]), "r"(a[1]), "r"(a[2]), "r"(a[3]), "r"(b[0]), "r"(b[1]));
}
__device__ __forceinline__ void cp16(void* d, const void* s, bool p) {
    uint32_t ds = (uint32_t)__cvta_generic_to_shared(d);
    int sz = p ? 16 : 0;
    asm volatile("cp.async.cg.shared.global [%0], [%1], 16, %2;"
                 :: "r"(ds), "l"(s), "r"(sz));
}
#define CP_COMMIT() asm volatile("cp.async.commit_group;")

// ---- tf32 pre-round (float4) ----------------------------------------------

__global__ void cvt4_k(const float4* __restrict__ in, float4* __restrict__ out,
                       int n4) {
    int i = blockIdx.x * blockDim.x + threadIdx.x;
    if (i >= n4) return;
    float4 v = in[i];
    v.x = tf32r(v.x); v.y = tf32r(v.y); v.z = tf32r(v.z); v.w = tf32r(v.w);
    out[i] = v;
}

// ---- CSR build -------------------------------------------------------------

__global__ void hist_k(const int* __restrict__ ei, int* __restrict__ cnt,
                       int E, int N) {
    int i = blockIdx.x * blockDim.x + threadIdx.x;
    if (i >= E + N) return;
    int dst = (i < E) ? ei[E + i] : (i - E);
    atomicAdd(&cnt[dst], 1);
}

__global__ void scan1(const int* __restrict__ cnt, int* __restrict__ rp,
                      int* __restrict__ bsum, int N) {
    __shared__ int sh[1024];
    int tid = threadIdx.x, gid = blockIdx.x * 1024 + tid;
    int v = (gid < N) ? cnt[gid] : 0;
    sh[tid] = v;
    __syncthreads();
    for (int off = 1; off < 1024; off <<= 1) {
        int t = (tid >= off) ? sh[tid - off] : 0;
        __syncthreads();
        sh[tid] += t;
        __syncthreads();
    }
    if (gid < N) rp[gid] = sh[tid] - v;
    if (tid == 1023) bsum[blockIdx.x] = sh[1023];
}

__global__ void scan2(int* __restrict__ bsum, int nb) {
    __shared__ int sh[1024];
    int tid = threadIdx.x;
    int v = (tid < nb) ? bsum[tid] : 0;
    sh[tid] = v;
    __syncthreads();
    for (int off = 1; off < 1024; off <<= 1) {
        int t = (tid >= off) ? sh[tid - off] : 0;
        __syncthreads();
        sh[tid] += t;
        __syncthreads();
    }
    if (tid < nb) bsum[tid] = sh[tid] - v;
}

__global__ void scan3(int* __restrict__ rp, const int* __restrict__ bsum,
                      int* __restrict__ cursor, int N, int ET) {
    int gid = blockIdx.x * blockDim.x + threadIdx.x;
    if (gid < N) {
        int r = rp[gid] + bsum[gid >> 10];
        rp[gid] = r;
        cursor[gid] = r;
    }
    if (gid == N) rp[N] = ET;
}

__global__ void scatter_k(const int* __restrict__ ei, int* __restrict__ cursor,
                          int* __restrict__ ssrc, int E, int N) {
    int i = blockIdx.x * blockDim.x + threadIdx.x;
    if (i >= E + N) return;
    int src, dst;
    if (i < E) { src = ei[i]; dst = ei[E + i]; }
    else       { src = dst = i - E; }
    int p = atomicAdd(&cursor[dst], 1);
    ssrc[p] = src;
}

// ---- TF32 GEMM, cp.async 3-stage: C[M,N] = A[M,K]*B[N,K]^T -----------------
// A, B already tf32-rounded.  K%16==0, N%128==0.

__global__ __launch_bounds__(256, 2)
void sgemm_tf32(const float* __restrict__ A, const float* __restrict__ B,
                float* __restrict__ Cm, int M, int N, int K) {
    constexpr int BM = 128, BN = 128, BK = 16, ST = 3, LDS = BK + 4;
    extern __shared__ float smn[];
    float (*As)[BM][LDS] = reinterpret_cast<float(*)[BM][LDS]>(smn);
    float (*Bs)[BN][LDS] =
        reinterpret_cast<float(*)[BN][LDS]>(smn + ST * BM * LDS);
    const int tid  = threadIdx.x;
    const int warp = tid >> 5, lane = tid & 31;
    const int wm = warp >> 2, wn = warp & 3;
    const int g = lane >> 2, t4 = lane & 3;
    const int bm = blockIdx.y * BM, bn = blockIdx.x * BN;
    const int r0 = tid >> 2, c40 = (tid & 3) << 2, r1 = r0 + 64;
    const bool pa0 = (bm + r0) < M, pa1 = (bm + r1) < M;

    auto load_stage = [&](int s, int k0) {
        cp16(&As[s][r0][c40], A + (size_t)(bm + r0) * K + k0 + c40, pa0);
        cp16(&As[s][r1][c40], A + (size_t)(bm + r1) * K + k0 + c40, pa1);
        cp16(&Bs[s][r0][c40], B + (size_t)(bn + r0) * K + k0 + c40, true);
        cp16(&Bs[s][r1][c40], B + (size_t)(bn + r1) * K + k0 + c40, true);
        CP_COMMIT();
    };

    float c[4][4][4] = {};

    load_stage(0, 0);
    load_stage(1, BK);
    int st = 0;

    for (int k0 = 0; k0 < K; k0 += BK) {
        asm volatile("cp.async.wait_group 1;");
        __syncthreads();
        int kn = k0 + 2 * BK;
        if (kn < K) load_stage(st == 0 ? 2 : st - 1, kn);
        else        CP_COMMIT();   // keep group counting uniform

        #pragma unroll
        for (int ks = 0; ks < BK; ks += 8) {
            uint32_t af[4][4], bf[4][2];
            #pragma unroll
            for (int mi = 0; mi < 4; mi++) {
                int row = wm * 64 + mi * 16;
                af[mi][0] = __float_as_uint(As[st][row + g][ks + t4]);
                af[mi][1] = __float_as_uint(As[st][row + g + 8][ks + t4]);
                af[mi][2] = __float_as_uint(As[st][row + g][ks + t4 + 4]);
                af[mi][3] = __float_as_uint(As[st][row + g + 8][ks + t4 + 4]);
            }
            #pragma unroll
            for (int ni = 0; ni < 4; ni++) {
                int col = wn * 32 + ni * 8;
                bf[ni][0] = __float_as_uint(Bs[st][col + g][ks + t4]);
                bf[ni][1] = __float_as_uint(Bs[st][col + g][ks + t4 + 4]);
            }
            #pragma unroll
            for (int mi = 0; mi < 4; mi++)
                #pragma unroll
                for (int ni = 0; ni < 4; ni++)
                    mma_tf32(c[mi][ni], af[mi], bf[ni]);
        }
        st = (st == ST - 1) ? 0 : st + 1;
    }

    #pragma unroll
    for (int mi = 0; mi < 4; mi++) {
        int row0 = bm + wm * 64 + mi * 16 + g;
        #pragma unroll
        for (int ni = 0; ni < 4; ni++) {
            int col = bn + wn * 32 + ni * 8 + t4 * 2;
            if (row0 < M)
                *reinterpret_cast<float2*>(Cm + (size_t)row0 * N + col) =
                    make_float2(c[mi][ni][0], c[mi][ni][1]);
            if (row0 + 8 < M)
                *reinterpret_cast<float2*>(Cm + (size_t)(row0 + 8) * N + col) =
                    make_float2(c[mi][ni][2], c[mi][ni][3]);
        }
    }
}

// ---- attention coefficients: s_n, d_n (warp per (node,head), float4) -------

__global__ void compute_sd(const float4* __restrict__ h,
                           const float4* __restrict__ a_src,
                           const float4* __restrict__ a_dst,
                           float* __restrict__ sn, float* __restrict__ dn,
                           int N, int H) {
    int w = (blockIdx.x * blockDim.x + threadIdx.x) >> 5;
    int lane = threadIdx.x & 31;
    if (w >= N * H) return;
    int n = w / H, hh = w - n * H;
    float4 v  = h[(size_t)n * H * 32 + hh * 32 + lane];
    float4 as = a_src[hh * 32 + lane];
    float4 ad = a_dst[hh * 32 + lane];
    float s = v.x * as.x + v.y * as.y + v.z * as.z + v.w * as.w;
    float d = v.x * ad.x + v.y * ad.y + v.z * ad.z + v.w * ad.w;
    #pragma unroll
    for (int o = 16; o; o >>= 1) {
        s += __shfl_down_sync(0xffffffffu, s, o);
        d += __shfl_down_sync(0xffffffffu, d, o);
    }
    if (lane == 0) { sn[w] = s; dn[w] = d; }
}

// ---- gather aggregation: warp per destination node, unroll-2 ---------------
// act==1: ELU + tf32 rounding (output feeds next GEMM).  No atomics.

template <int H>
__global__ void aggregate_k(const int* __restrict__ rp,
                            const int* __restrict__ ssrc,
                            const float4* __restrict__ hf,
                            const float* __restrict__ sn,
                            const float* __restrict__ dn,
                            const float4* __restrict__ bias, int act,
                            float4* __restrict__ outp, int N) {
    constexpr int J = H * 32;
    constexpr int PER = J / 32;
    int n = (blockIdx.x * blockDim.x + threadIdx.x) >> 5;
    int lane = threadIdx.x & 31;
    if (n >= N) return;
    const int head = (H == 1) ? 0 : (lane >> 3);

    float dnv = (lane < H) ? dn[n * H + lane] : 0.f;

    float4 acc[PER];
    #pragma unroll
    for (int it = 0; it < PER; it++) acc[it] = make_float4(0.f, 0.f, 0.f, 0.f);
    float den = 0.f;

    const int s0 = rp[n], s1 = rp[n + 1];
    int p = s0;
    for (; p + 1 < s1; p += 2) {
        int srcA = __ldg(ssrc + p);
        int srcB = __ldg(ssrc + p + 1);
        float exvA = 0.f, exvB = 0.f;
        if (lane < H) {
            float eA = sn[srcA * H + lane] + dnv;
            float eB = sn[srcB * H + lane] + dnv;
            eA = eA > 0.f ? eA : 0.2f * eA;
            eB = eB > 0.f ? eB : 0.2f * eB;
            exvA = __expf(eA);
            exvB = __expf(eB);
        }
        float exA = __shfl_sync(0xffffffffu, exvA, head);
        float exB = __shfl_sync(0xffffffffu, exvB, head);
        den += exA + exB;
        const float4* ra = hf + (size_t)srcA * J + lane * PER;
        const float4* rb = hf + (size_t)srcB * J + lane * PER;
        #pragma unroll
        for (int it = 0; it < PER; it++) {
            float4 va = __ldg(ra + it);
            float4 vb = __ldg(rb + it);
            acc[it].x += exA * va.x + exB * vb.x;
            acc[it].y += exA * va.y + exB * vb.y;
            acc[it].z += exA * va.z + exB * vb.z;
            acc[it].w += exA * va.w + exB * vb.w;
        }
    }
    if (p < s1) {
        int src = __ldg(ssrc + p);
        float exv = 0.f;
        if (lane < H) {
            float e = sn[src * H + lane] + dnv;
            e = e > 0.f ? e : 0.2f * e;
            exv = __expf(e);
        }
        float ex = __shfl_sync(0xffffffffu, exv, head);
        den += ex;
        const float4* hrow = hf + (size_t)src * J + lane * PER;
        #pragma unroll
        for (int it = 0; it < PER; it++) {
            float4 v = __ldg(hrow + it);
            acc[it].x += ex * v.x; acc[it].y += ex * v.y;
            acc[it].z += ex * v.z; acc[it].w += ex * v.w;
        }
    }

    float sc = 1.f / (den + 1e-16f);
    float4* orow = outp + (size_t)n * J + lane * PER;
    #pragma unroll
    for (int it = 0; it < PER; it++) {
        float4 bb = bias[lane * PER + it];
        float4 v;
        v.x = acc[it].x * sc + bb.x;
        v.y = acc[it].y * sc + bb.y;
        v.z = acc[it].z * sc + bb.z;
        v.w = acc[it].w * sc + bb.w;
        if (act) {
            v.x = v.x > 0.f ? v.x : (__expf(v.x) - 1.f);
            v.y = v.y > 0.f ? v.y : (__expf(v.y) - 1.f);
            v.z = v.z > 0.f ? v.z : (__expf(v.z) - 1.f);
            v.w = v.w > 0.f ? v.w : (__expf(v.w) - 1.f);
            v.x = tf32r(v.x); v.y = tf32r(v.y);
            v.z = tf32r(v.z); v.w = tf32r(v.w);
        }
        orow[it] = v;
    }
}

// ---- MLP head --------------------------------------------------------------

__global__ __launch_bounds__(64)
void head_kernel(const float* __restrict__ emb, const float* __restrict__ Wh1,
                 const float* __restrict__ bh1, const float* __restrict__ Wh2,
                 const float* __restrict__ bh2, float* __restrict__ scores, int N) {
    int n = blockIdx.x;
    int j = threadIdx.x;
    __shared__ float er[128];
    __shared__ float zs[64];
    er[j]      = emb[(size_t)n * 128 + j];
    er[j + 64] = emb[(size_t)n * 128 + 64 + j];
    __syncthreads();
    const float* w = Wh1 + j * 128;
    float s = 0.f;
    #pragma unroll 8
    for (int k = 0; k < 128; k++) s += er[k] * w[k];
    s += bh1[j];
    s = fmaxf(s, 0.f);
    zs[j] = s * Wh2[j];
    __syncthreads();
    if (j < 32) {
        float v = zs[j] + zs[j + 32];
        #pragma unroll
        for (int o = 16; o; o >>= 1) v += __shfl_down_sync(0xffffffffu, v, o);
        if (j == 0) scores[n] = 1.f / (1.f + __expf(-(v + bh2[0])));
    }
}

// ---------------------------------------------------------------------------

extern "C" void kernel_launch(void* const* d_in, const int* in_sizes, int n_in,
                              void* d_out, int out_size) {
    const float* x  = (const float*)d_in[0];
    const int*   ei = (const int*)d_in[1];
    const float *W1 = (const float*)d_in[2],  *as1 = (const float*)d_in[3],
                *ad1 = (const float*)d_in[4], *b1 = (const float*)d_in[5];
    const float *W2 = (const float*)d_in[6],  *as2 = (const float*)d_in[7],
                *ad2 = (const float*)d_in[8], *b2 = (const float*)d_in[9];
    const float *W3 = (const float*)d_in[10], *as3 = (const float*)d_in[11],
                *ad3 = (const float*)d_in[12], *b3 = (const float*)d_in[13];
    const float *Wh1 = (const float*)d_in[14], *bh1 = (const float*)d_in[15],
                *Wh2 = (const float*)d_in[16], *bh2 = (const float*)d_in[17];
    float* out = (float*)d_out;

    const int N = in_sizes[0] / 256;
    const int E = in_sizes[1] / 2;
    const int ET = E + N;

    float4 *gh4, *gout4, *wc4;
    float *snp, *dnp;
    int *cnt, *rp, *cursor, *ssrc, *bsum;
    cudaGetSymbolAddress((void**)&gh4,    g_h_buf4);
    cudaGetSymbolAddress((void**)&gout4,  g_out_buf4);
    cudaGetSymbolAddress((void**)&wc4,    g_wc4);
    cudaGetSymbolAddress((void**)&snp,    g_sn_buf);
    cudaGetSymbolAddress((void**)&dnp,    g_dn_buf);
    cudaGetSymbolAddress((void**)&cnt,    g_cnt);
    cudaGetSymbolAddress((void**)&rp,     g_rp);
    cudaGetSymbolAddress((void**)&cursor, g_cursor);
    cudaGetSymbolAddress((void**)&ssrc,   g_ssrc);
    cudaGetSymbolAddress((void**)&bsum,   g_bsum);
    float* gout = (float*)gout4;

    auto cdiv = [](int a, int b) { return (a + b - 1) / b; };

    constexpr int SMEM_GEMM = 3 * 128 * 20 * 2 * 4;   // 61440 B
    cudaFuncSetAttribute(sgemm_tf32,
                         cudaFuncAttributeMaxDynamicSharedMemorySize, SMEM_GEMM);

    // ---- pre-round weights + x to tf32 bits ----
    float* wc1 = (float*)wc4;                 // 131072 floats
    float* wc2 = wc1 + 131072;                // 262144 floats
    float* wc3 = wc2 + 262144;                // 65536 floats
    cvt4_k<<<cdiv(131072 / 4, 256), 256>>>((const float4*)W1, (float4*)wc1, 131072 / 4);
    cvt4_k<<<cdiv(262144 / 4, 256), 256>>>((const float4*)W2, (float4*)wc2, 262144 / 4);
    cvt4_k<<<cdiv(65536 / 4, 256), 256>>>((const float4*)W3, (float4*)wc3, 65536 / 4);
    float* xc = gout;                         // reuse layer buffer pre-layer1
    cvt4_k<<<cdiv(N * 64, 256), 256>>>((const float4*)x, (float4*)xc, N * 64);

    // ---- CSR build (once; reused by all 3 layers) ----
    const int nb = cdiv(N, 1024);
    cudaMemsetAsync(cnt, 0, (size_t)N * 4);
    hist_k<<<cdiv(ET, 256), 256>>>(ei, cnt, E, N);
    scan1<<<nb, 1024>>>(cnt, rp, bsum, N);
    scan2<<<1, 1024>>>(bsum, nb);
    scan3<<<cdiv(N + 1, 256), 256>>>(rp, bsum, cursor, N, ET);
    scatter_k<<<cdiv(ET, 256), 256>>>(ei, cursor, ssrc, E, N);

    // ---- generic GAT layer ----
    auto run_layer = [&](const float* fin, int Fin, const float* W,
                         const float* as, const float* ad, const float* bb,
                         int H, int act, float* finalout) {
        const int HC = H * 128;
        dim3 gg(cdiv(HC, 128), cdiv(N, 128));
        sgemm_tf32<<<gg, 256, SMEM_GEMM>>>(fin, W, (float*)gh4, N, HC, Fin);
        compute_sd<<<cdiv(N * H * 32, 256), 256>>>(
            (const float4*)gh4, (const float4*)as, (const float4*)ad,
            snp, dnp, N, H);
        if (H == 4)
            aggregate_k<4><<<cdiv(N * 32, 256), 256>>>(
                rp, ssrc, gh4, snp, dnp, (const float4*)bb, act,
                (float4*)finalout, N);
        else
            aggregate_k<1><<<cdiv(N * 32, 256), 256>>>(
                rp, ssrc, gh4, snp, dnp, (const float4*)bb, act,
                (float4*)finalout, N);
    };

    run_layer(xc,   256, wc1, as1, ad1, b1, 4, 1, gout);
    run_layer(gout, 512, wc2, as2, ad2, b2, 4, 1, gout);
    run_layer(gout, 512, wc3, as3, ad3, b3, 1, 0, out);

    head_kernel<<<N, 64>>>(out, Wh1, bh1, Wh2, bh2, out + (size_t)N * 128, N);
}

// round 14
// speedup vs baseline: 1.9100x; 1.0017x over previous
#include <cuda_runtime.h>
#include <cstdint>

// ---------------------------------------------------------------------------
// AllocationGNN: 3x GATConv + MLP head.  R13:
//  - L2 residency engineering: h buffer written/read with evict_last policy,
//    aggregate output written with evict_first (streaming) so the ~17x reuse
//    of h rows during gather aggregation is served from L2, not DRAM.
//  - everything else as R12 (cp.async TF32 GEMM, CSR gather aggregation).
// ---------------------------------------------------------------------------

#define NMAX 50000
#define EMAX 800000
#define ETMAX (EMAX + NMAX)

__device__ float4 g_h_buf4[(size_t)NMAX * 128];    // N*512 floats (GEMM out)
__device__ float4 g_out_buf4[(size_t)NMAX * 128];  // N*512 floats (layer I/O)
__device__ float  g_sn_buf[NMAX * 4];
__device__ float  g_dn_buf[NMAX * 4];
__device__ float4 g_wc4[114688];                   // tf32-rounded W1|W2|W3
__device__ int    g_cnt[NMAX];
__device__ int    g_rp[NMAX + 1];
__device__ int    g_cursor[NMAX];
__device__ int    g_ssrc[ETMAX];
__device__ int    g_bsum[1024];

// ---- cache-policy helpers --------------------------------------------------

__device__ __forceinline__ uint64_t pol_last() {
    uint64_t p;
    asm("createpolicy.fractional.L2::evict_last.b64 %0, 1.0;" : "=l"(p));
    return p;
}
__device__ __forceinline__ uint64_t pol_first() {
    uint64_t p;
    asm("createpolicy.fractional.L2::evict_first.b64 %0, 1.0;" : "=l"(p));
    return p;
}
__device__ __forceinline__ float4 ld4_hint(const float4* a, uint64_t pol) {
    float4 v;
    asm("ld.global.nc.L2::cache_hint.v4.f32 {%0,%1,%2,%3}, [%4], %5;"
        : "=f"(v.x), "=f"(v.y), "=f"(v.z), "=f"(v.w)
        : "l"(a), "l"(pol));
    return v;
}
__device__ __forceinline__ void st4_hint(float4* a, float4 v, uint64_t pol) {
    asm volatile("st.global.L2::cache_hint.v4.f32 [%0], {%1,%2,%3,%4}, %5;"
                 :: "l"(a), "f"(v.x), "f"(v.y), "f"(v.z), "f"(v.w), "l"(pol)
                 : "memory");
}
__device__ __forceinline__ void st2_hint(float* a, float x, float y,
                                         uint64_t pol) {
    asm volatile("st.global.L2::cache_hint.v2.f32 [%0], {%1,%2}, %3;"
                 :: "l"(a), "f"(x), "f"(y), "l"(pol) : "memory");
}

// ---- misc helpers ----------------------------------------------------------

__device__ __forceinline__ uint32_t f2tf32(float f) {
    uint32_t r;
    asm("cvt.rna.tf32.f32 %0, %1;" : "=r"(r) : "f"(f));
    return r;
}
__device__ __forceinline__ float tf32r(float f) {
    return __uint_as_float(f2tf32(f));
}
__device__ __forceinline__ void mma_tf32(float* c, const uint32_t* a,
                                         const uint32_t* b) {
    asm volatile(
        "mma.sync.aligned.m16n8k8.row.col.f32.tf32.tf32.f32 "
        "{%0,%1,%2,%3}, {%4,%5,%6,%7}, {%8,%9}, {%0,%1,%2,%3};"
        : "+f"(c[0]), "+f"(c[1]), "+f"(c[2]), "+f"(c[3])
        : "r"(a[0]), "r"(a[1]), "r"(a[2]), "r"(a[3]), "r"(b[0]), "r"(b[1]));
}
__device__ __forceinline__ void cp16(void* d, const void* s, bool p) {
    uint32_t ds = (uint32_t)__cvta_generic_to_shared(d);
    int sz = p ? 16 : 0;
    asm volatile("cp.async.cg.shared.global [%0], [%1], 16, %2;"
                 :: "r"(ds), "l"(s), "r"(sz));
}
#define CP_COMMIT() asm volatile("cp.async.commit_group;")

// ---- tf32 pre-round (float4) ----------------------------------------------

__global__ void cvt4_k(const float4* __restrict__ in, float4* __restrict__ out,
                       int n4) {
    int i = blockIdx.x * blockDim.x + threadIdx.x;
    if (i >= n4) return;
    float4 v = in[i];
    v.x = tf32r(v.x); v.y = tf32r(v.y); v.z = tf32r(v.z); v.w = tf32r(v.w);
    out[i] = v;
}

// ---- CSR build -------------------------------------------------------------

__global__ void hist_k(const int* __restrict__ ei, int* __restrict__ cnt,
                       int E, int N) {
    int i = blockIdx.x * blockDim.x + threadIdx.x;
    if (i >= E + N) return;
    int dst = (i < E) ? ei[E + i] : (i - E);
    atomicAdd(&cnt[dst], 1);
}

__global__ void scan1(const int* __restrict__ cnt, int* __restrict__ rp,
                      int* __restrict__ bsum, int N) {
    __shared__ int sh[1024];
    int tid = threadIdx.x, gid = blockIdx.x * 1024 + tid;
    int v = (gid < N) ? cnt[gid] : 0;
    sh[tid] = v;
    __syncthreads();
    for (int off = 1; off < 1024; off <<= 1) {
        int t = (tid >= off) ? sh[tid - off] : 0;
        __syncthreads();
        sh[tid] += t;
        __syncthreads();
    }
    if (gid < N) rp[gid] = sh[tid] - v;
    if (tid == 1023) bsum[blockIdx.x] = sh[1023];
}

__global__ void scan2(int* __restrict__ bsum, int nb) {
    __shared__ int sh[1024];
    int tid = threadIdx.x;
    int v = (tid < nb) ? bsum[tid] : 0;
    sh[tid] = v;
    __syncthreads();
    for (int off = 1; off < 1024; off <<= 1) {
        int t = (tid >= off) ? sh[tid - off] : 0;
        __syncthreads();
        sh[tid] += t;
        __syncthreads();
    }
    if (tid < nb) bsum[tid] = sh[tid] - v;
}

__global__ void scan3(int* __restrict__ rp, const int* __restrict__ bsum,
                      int* __restrict__ cursor, int N, int ET) {
    int gid = blockIdx.x * blockDim.x + threadIdx.x;
    if (gid < N) {
        int r = rp[gid] + bsum[gid >> 10];
        rp[gid] = r;
        cursor[gid] = r;
    }
    if (gid == N) rp[N] = ET;
}

__global__ void scatter_k(const int* __restrict__ ei, int* __restrict__ cursor,
                          int* __restrict__ ssrc, int E, int N) {
    int i = blockIdx.x * blockDim.x + threadIdx.x;
    if (i >= E + N) return;
    int src, dst;
    if (i < E) { src = ei[i]; dst = ei[E + i]; }
    else       { src = dst = i - E; }
    int p = atomicAdd(&cursor[dst], 1);
    ssrc[p] = src;
}

// ---- TF32 GEMM, cp.async 3-stage: C[M,N] = A[M,K]*B[N,K]^T -----------------
// A, B already tf32-rounded.  C stored with evict_last (stays in L2 for the
// downstream sd + aggregation reads).

__global__ __launch_bounds__(256, 2)
void sgemm_tf32(const float* __restrict__ A, const float* __restrict__ B,
                float* __restrict__ Cm, int M, int N, int K) {
    constexpr int BM = 128, BN = 128, BK = 16, ST = 3, LDS = BK + 4;
    extern __shared__ float smn[];
    float (*As)[BM][LDS] = reinterpret_cast<float(*)[BM][LDS]>(smn);
    float (*Bs)[BN][LDS] =
        reinterpret_cast<float(*)[BN][LDS]>(smn + ST * BM * LDS);
    const int tid  = threadIdx.x;
    const int warp = tid >> 5, lane = tid & 31;
    const int wm = warp >> 2, wn = warp & 3;
    const int g = lane >> 2, t4 = lane & 3;
    const int bm = blockIdx.y * BM, bn = blockIdx.x * BN;
    const int r0 = tid >> 2, c40 = (tid & 3) << 2, r1 = r0 + 64;
    const bool pa0 = (bm + r0) < M, pa1 = (bm + r1) < M;

    auto load_stage = [&](int s, int k0) {
        cp16(&As[s][r0][c40], A + (size_t)(bm + r0) * K + k0 + c40, pa0);
        cp16(&As[s][r1][c40], A + (size_t)(bm + r1) * K + k0 + c40, pa1);
        cp16(&Bs[s][r0][c40], B + (size_t)(bn + r0) * K + k0 + c40, true);
        cp16(&Bs[s][r1][c40], B + (size_t)(bn + r1) * K + k0 + c40, true);
        CP_COMMIT();
    };

    float c[4][4][4] = {};

    load_stage(0, 0);
    load_stage(1, BK);
    int st = 0;

    for (int k0 = 0; k0 < K; k0 += BK) {
        asm volatile("cp.async.wait_group 1;");
        __syncthreads();
        int kn = k0 + 2 * BK;
        if (kn < K) load_stage(st == 0 ? 2 : st - 1, kn);
        else        CP_COMMIT();

        #pragma unroll
        for (int ks = 0; ks < BK; ks += 8) {
            uint32_t af[4][4], bf[4][2];
            #pragma unroll
            for (int mi = 0; mi < 4; mi++) {
                int row = wm * 64 + mi * 16;
                af[mi][0] = __float_as_uint(As[st][row + g][ks + t4]);
                af[mi][1] = __float_as_uint(As[st][row + g + 8][ks + t4]);
                af[mi][2] = __float_as_uint(As[st][row + g][ks + t4 + 4]);
                af[mi][3] = __float_as_uint(As[st][row + g + 8][ks + t4 + 4]);
            }
            #pragma unroll
            for (int ni = 0; ni < 4; ni++) {
                int col = wn * 32 + ni * 8;
                bf[ni][0] = __float_as_uint(Bs[st][col + g][ks + t4]);
                bf[ni][1] = __float_as_uint(Bs[st][col + g][ks + t4 + 4]);
            }
            #pragma unroll
            for (int mi = 0; mi < 4; mi++)
                #pragma unroll
                for (int ni = 0; ni < 4; ni++)
                    mma_tf32(c[mi][ni], af[mi], bf[ni]);
        }
        st = (st == ST - 1) ? 0 : st + 1;
    }

    uint64_t pl = pol_last();
    #pragma unroll
    for (int mi = 0; mi < 4; mi++) {
        int row0 = bm + wm * 64 + mi * 16 + g;
        #pragma unroll
        for (int ni = 0; ni < 4; ni++) {
            int col = bn + wn * 32 + ni * 8 + t4 * 2;
            if (row0 < M)
                st2_hint(Cm + (size_t)row0 * N + col,
                         c[mi][ni][0], c[mi][ni][1], pl);
            if (row0 + 8 < M)
                st2_hint(Cm + (size_t)(row0 + 8) * N + col,
                         c[mi][ni][2], c[mi][ni][3], pl);
        }
    }
}

// ---- attention coefficients: s_n, d_n (warp per (node,head), float4) -------

__global__ void compute_sd(const float4* __restrict__ h,
                           const float4* __restrict__ a_src,
                           const float4* __restrict__ a_dst,
                           float* __restrict__ sn, float* __restrict__ dn,
                           int N, int H) {
    int w = (blockIdx.x * blockDim.x + threadIdx.x) >> 5;
    int lane = threadIdx.x & 31;
    if (w >= N * H) return;
    int n = w / H, hh = w - n * H;
    uint64_t pl = pol_last();
    float4 v  = ld4_hint(h + (size_t)n * H * 32 + hh * 32 + lane, pl);
    float4 as = a_src[hh * 32 + lane];
    float4 ad = a_dst[hh * 32 + lane];
    float s = v.x * as.x + v.y * as.y + v.z * as.z + v.w * as.w;
    float d = v.x * ad.x + v.y * ad.y + v.z * ad.z + v.w * ad.w;
    #pragma unroll
    for (int o = 16; o; o >>= 1) {
        s += __shfl_down_sync(0xffffffffu, s, o);
        d += __shfl_down_sync(0xffffffffu, d, o);
    }
    if (lane == 0) { sn[w] = s; dn[w] = d; }
}

// ---- gather aggregation: warp per destination node, unroll-2 ---------------
// h reads: evict_last (keep resident; ~17x reuse).  out writes: evict_first.

template <int H>
__global__ void aggregate_k(const int* __restrict__ rp,
                            const int* __restrict__ ssrc,
                            const float4* __restrict__ hf,
                            const float* __restrict__ sn,
                            const float* __restrict__ dn,
                            const float4* __restrict__ bias, int act,
                            float4* __restrict__ outp, int N) {
    constexpr int J = H * 32;
    constexpr int PER = J / 32;
    int n = (blockIdx.x * blockDim.x + threadIdx.x) >> 5;
    int lane = threadIdx.x & 31;
    if (n >= N) return;
    const int head = (H == 1) ? 0 : (lane >> 3);
    uint64_t pl = pol_last();
    uint64_t pf = pol_first();

    float dnv = (lane < H) ? dn[n * H + lane] : 0.f;

    float4 acc[PER];
    #pragma unroll
    for (int it = 0; it < PER; it++) acc[it] = make_float4(0.f, 0.f, 0.f, 0.f);
    float den = 0.f;

    const int s0 = rp[n], s1 = rp[n + 1];
    int p = s0;
    for (; p + 1 < s1; p += 2) {
        int srcA = __ldg(ssrc + p);
        int srcB = __ldg(ssrc + p + 1);
        float exvA = 0.f, exvB = 0.f;
        if (lane < H) {
            float eA = sn[srcA * H + lane] + dnv;
            float eB = sn[srcB * H + lane] + dnv;
            eA = eA > 0.f ? eA : 0.2f * eA;
            eB = eB > 0.f ? eB : 0.2f * eB;
            exvA = __expf(eA);
            exvB = __expf(eB);
        }
        float exA = __shfl_sync(0xffffffffu, exvA, head);
        float exB = __shfl_sync(0xffffffffu, exvB, head);
        den += exA + exB;
        const float4* ra = hf + (size_t)srcA * J + lane * PER;
        const float4* rb = hf + (size_t)srcB * J + lane * PER;
        #pragma unroll
        for (int it = 0; it < PER; it++) {
            float4 va = ld4_hint(ra + it, pl);
            float4 vb = ld4_hint(rb + it, pl);
            acc[it].x += exA * va.x + exB * vb.x;
            acc[it].y += exA * va.y + exB * vb.y;
            acc[it].z += exA * va.z + exB * vb.z;
            acc[it].w += exA * va.w + exB * vb.w;
        }
    }
    if (p < s1) {
        int src = __ldg(ssrc + p);
        float exv = 0.f;
        if (lane < H) {
            float e = sn[src * H + lane] + dnv;
            e = e > 0.f ? e : 0.2f * e;
            exv = __expf(e);
        }
        float ex = __shfl_sync(0xffffffffu, exv, head);
        den += ex;
        const float4* hrow = hf + (size_t)src * J + lane * PER;
        #pragma unroll
        for (int it = 0; it < PER; it++) {
            float4 v = ld4_hint(hrow + it, pl);
            acc[it].x += ex * v.x; acc[it].y += ex * v.y;
            acc[it].z += ex * v.z; acc[it].w += ex * v.w;
        }
    }

    float sc = 1.f / (den + 1e-16f);
    float4* orow = outp + (size_t)n * J + lane * PER;
    #pragma unroll
    for (int it = 0; it < PER; it++) {
        float4 bb = bias[lane * PER + it];
        float4 v;
        v.x = acc[it].x * sc + bb.x;
        v.y = acc[it].y * sc + bb.y;
        v.z = acc[it].z * sc + bb.z;
        v.w = acc[it].w * sc + bb.w;
        if (act) {
            v.x = v.x > 0.f ? v.x : (__expf(v.x) - 1.f);
            v.y = v.y > 0.f ? v.y : (__expf(v.y) - 1.f);
            v.z = v.z > 0.f ? v.z : (__expf(v.z) - 1.f);
            v.w = v.w > 0.f ? v.w : (__expf(v.w) - 1.f);
            v.x = tf32r(v.x); v.y = tf32r(v.y);
            v.z = tf32r(v.z); v.w = tf32r(v.w);
            st4_hint(orow + it, v, pf);
        } else {
            orow[it] = v;   // final embeddings -> d_out, default policy
        }
    }
}

// ---- MLP head --------------------------------------------------------------

__global__ __launch_bounds__(64)
void head_kernel(const float* __restrict__ emb, const float* __restrict__ Wh1,
                 const float* __restrict__ bh1, const float* __restrict__ Wh2,
                 const float* __restrict__ bh2, float* __restrict__ scores, int N) {
    int n = blockIdx.x;
    int j = threadIdx.x;
    __shared__ float er[128];
    __shared__ float zs[64];
    er[j]      = emb[(size_t)n * 128 + j];
    er[j + 64] = emb[(size_t)n * 128 + 64 + j];
    __syncthreads();
    const float* w = Wh1 + j * 128;
    float s = 0.f;
    #pragma unroll 8
    for (int k = 0; k < 128; k++) s += er[k] * w[k];
    s += bh1[j];
    s = fmaxf(s, 0.f);
    zs[j] = s * Wh2[j];
    __syncthreads();
    if (j < 32) {
        float v = zs[j] + zs[j + 32];
        #pragma unroll
        for (int o = 16; o; o >>= 1) v += __shfl_down_sync(0xffffffffu, v, o);
        if (j == 0) scores[n] = 1.f / (1.f + __expf(-(v + bh2[0])));
    }
}

// ---------------------------------------------------------------------------

extern "C" void kernel_launch(void* const* d_in, const int* in_sizes, int n_in,
                              void* d_out, int out_size) {
    const float* x  = (const float*)d_in[0];
    const int*   ei = (const int*)d_in[1];
    const float *W1 = (const float*)d_in[2],  *as1 = (const float*)d_in[3],
                *ad1 = (const float*)d_in[4], *b1 = (const float*)d_in[5];
    const float *W2 = (const float*)d_in[6],  *as2 = (const float*)d_in[7],
                *ad2 = (const float*)d_in[8], *b2 = (const float*)d_in[9];
    const float *W3 = (const float*)d_in[10], *as3 = (const float*)d_in[11],
                *ad3 = (const float*)d_in[12], *b3 = (const float*)d_in[13];
    const float *Wh1 = (const float*)d_in[14], *bh1 = (const float*)d_in[15],
                *Wh2 = (const float*)d_in[16], *bh2 = (const float*)d_in[17];
    float* out = (float*)d_out;

    const int N = in_sizes[0] / 256;
    const int E = in_sizes[1] / 2;
    const int ET = E + N;

    float4 *gh4, *gout4, *wc4;
    float *snp, *dnp;
    int *cnt, *rp, *cursor, *ssrc, *bsum;
    cudaGetSymbolAddress((void**)&gh4,    g_h_buf4);
    cudaGetSymbolAddress((void**)&gout4,  g_out_buf4);
    cudaGetSymbolAddress((void**)&wc4,    g_wc4);
    cudaGetSymbolAddress((void**)&snp,    g_sn_buf);
    cudaGetSymbolAddress((void**)&dnp,    g_dn_buf);
    cudaGetSymbolAddress((void**)&cnt,    g_cnt);
    cudaGetSymbolAddress((void**)&rp,     g_rp);
    cudaGetSymbolAddress((void**)&cursor, g_cursor);
    cudaGetSymbolAddress((void**)&ssrc,   g_ssrc);
    cudaGetSymbolAddress((void**)&bsum,   g_bsum);
    float* gout = (float*)gout4;

    auto cdiv = [](int a, int b) { return (a + b - 1) / b; };

    constexpr int SMEM_GEMM = 3 * 128 * 20 * 2 * 4;   // 61440 B
    cudaFuncSetAttribute(sgemm_tf32,
                         cudaFuncAttributeMaxDynamicSharedMemorySize, SMEM_GEMM);

    // ---- pre-round weights + x to tf32 bits ----
    float* wc1 = (float*)wc4;
    float* wc2 = wc1 + 131072;
    float* wc3 = wc2 + 262144;
    cvt4_k<<<cdiv(131072 / 4, 256), 256>>>((const float4*)W1, (float4*)wc1, 131072 / 4);
    cvt4_k<<<cdiv(262144 / 4, 256), 256>>>((const float4*)W2, (float4*)wc2, 262144 / 4);
    cvt4_k<<<cdiv(65536 / 4, 256), 256>>>((const float4*)W3, (float4*)wc3, 65536 / 4);
    float* xc = gout;
    cvt4_k<<<cdiv(N * 64, 256), 256>>>((const float4*)x, (float4*)xc, N * 64);

    // ---- CSR build (once; reused by all 3 layers) ----
    const int nb = cdiv(N, 1024);
    cudaMemsetAsync(cnt, 0, (size_t)N * 4);
    hist_k<<<cdiv(ET, 256), 256>>>(ei, cnt, E, N);
    scan1<<<nb, 1024>>>(cnt, rp, bsum, N);
    scan2<<<1, 1024>>>(bsum, nb);
    scan3<<<cdiv(N + 1, 256), 256>>>(rp, bsum, cursor, N, ET);
    scatter_k<<<cdiv(ET, 256), 256>>>(ei, cursor, ssrc, E, N);

    // ---- generic GAT layer ----
    auto run_layer = [&](const float* fin, int Fin, const float* W,
                         const float* as, const float* ad, const float* bb,
                         int H, int act, float* finalout) {
        const int HC = H * 128;
        dim3 gg(cdiv(HC, 128), cdiv(N, 128));
        sgemm_tf32<<<gg, 256, SMEM_GEMM>>>(fin, W, (float*)gh4, N, HC, Fin);
        compute_sd<<<cdiv(N * H * 32, 256), 256>>>(
            (const float4*)gh4, (const float4*)as, (const float4*)ad,
            snp, dnp, N, H);
        if (H == 4)
            aggregate_k<4><<<cdiv(N * 32, 256), 256>>>(
                rp, ssrc, gh4, snp, dnp, (const float4*)bb, act,
                (float4*)finalout, N);
        else
            aggregate_k<1><<<cdiv(N * 32, 256), 256>>>(
                rp, ssrc, gh4, snp, dnp, (const float4*)bb, act,
                (float4*)finalout, N);
    };

    run_layer(xc,   256, wc1, as1, ad1, b1, 4, 1, gout);
    run_layer(gout, 512, wc2, as2, ad2, b2, 4, 1, gout);
    run_layer(gout, 512, wc3, as3, ad3, b3, 1, 0, out);

    head_kernel<<<N, 64>>>(out, Wh1, bh1, Wh2, bh2, out + (size_t)N * 128, N);
}

// round 15
// speedup vs baseline: 2.0243x; 1.0598x over previous
#include <cuda_runtime.h>
#include <cstdint>

// ---------------------------------------------------------------------------
// AllocationGNN: 3x GATConv + MLP head.  R15:
//  - head-split aggregation: H=4 layers aggregate in two passes over head
//    pairs; per-pass gather working set = 51 MB (fits L2, ~17x reuse) instead
//    of 102 MB (DRAM thrash).  Bit-identical math per output element.
//  - everything else as R13 (cp.async TF32 GEMM, CSR gather, tf32 pre-round).
// ---------------------------------------------------------------------------

#define NMAX 50000
#define EMAX 800000
#define ETMAX (EMAX + NMAX)

__device__ float4 g_h_buf4[(size_t)NMAX * 128];    // N*512 floats (GEMM out)
__device__ float4 g_out_buf4[(size_t)NMAX * 128];  // N*512 floats (layer I/O)
__device__ float  g_sn_buf[NMAX * 4];
__device__ float  g_dn_buf[NMAX * 4];
__device__ float4 g_wc4[114688];                   // tf32-rounded W1|W2|W3
__device__ int    g_cnt[NMAX];
__device__ int    g_rp[NMAX + 1];
__device__ int    g_cursor[NMAX];
__device__ int    g_ssrc[ETMAX];
__device__ int    g_bsum[1024];

// ---- cache-policy helpers --------------------------------------------------

__device__ __forceinline__ uint64_t pol_last() {
    uint64_t p;
    asm("createpolicy.fractional.L2::evict_last.b64 %0, 1.0;" : "=l"(p));
    return p;
}
__device__ __forceinline__ uint64_t pol_first() {
    uint64_t p;
    asm("createpolicy.fractional.L2::evict_first.b64 %0, 1.0;" : "=l"(p));
    return p;
}
__device__ __forceinline__ float4 ld4_hint(const float4* a, uint64_t pol) {
    float4 v;
    asm("ld.global.nc.L2::cache_hint.v4.f32 {%0,%1,%2,%3}, [%4], %5;"
        : "=f"(v.x), "=f"(v.y), "=f"(v.z), "=f"(v.w)
        : "l"(a), "l"(pol));
    return v;
}
__device__ __forceinline__ void st4_hint(float4* a, float4 v, uint64_t pol) {
    asm volatile("st.global.L2::cache_hint.v4.f32 [%0], {%1,%2,%3,%4}, %5;"
                 :: "l"(a), "f"(v.x), "f"(v.y), "f"(v.z), "f"(v.w), "l"(pol)
                 : "memory");
}
__device__ __forceinline__ void st2_hint(float* a, float x, float y,
                                         uint64_t pol) {
    asm volatile("st.global.L2::cache_hint.v2.f32 [%0], {%1,%2}, %3;"
                 :: "l"(a), "f"(x), "f"(y), "l"(pol) : "memory");
}

// ---- misc helpers ----------------------------------------------------------

__device__ __forceinline__ uint32_t f2tf32(float f) {
    uint32_t r;
    asm("cvt.rna.tf32.f32 %0, %1;" : "=r"(r) : "f"(f));
    return r;
}
__device__ __forceinline__ float tf32r(float f) {
    return __uint_as_float(f2tf32(f));
}
__device__ __forceinline__ void mma_tf32(float* c, const uint32_t* a,
                                         const uint32_t* b) {
    asm volatile(
        "mma.sync.aligned.m16n8k8.row.col.f32.tf32.tf32.f32 "
        "{%0,%1,%2,%3}, {%4,%5,%6,%7}, {%8,%9}, {%0,%1,%2,%3};"
        : "+f"(c[0]), "+f"(c[1]), "+f"(c[2]), "+f"(c[3])
        : "r"(a[0]), "r"(a[1]), "r"(a[2]), "r"(a[3]), "r"(b[0]), "r"(b[1]));
}
__device__ __forceinline__ void cp16(void* d, const void* s, bool p) {
    uint32_t ds = (uint32_t)__cvta_generic_to_shared(d);
    int sz = p ? 16 : 0;
    asm volatile("cp.async.cg.shared.global [%0], [%1], 16, %2;"
                 :: "r"(ds), "l"(s), "r"(sz));
}
#define CP_COMMIT() asm volatile("cp.async.commit_group;")

// ---- tf32 pre-round (float4) ----------------------------------------------

__global__ void cvt4_k(const float4* __restrict__ in, float4* __restrict__ out,
                       int n4) {
    int i = blockIdx.x * blockDim.x + threadIdx.x;
    if (i >= n4) return;
    float4 v = in[i];
    v.x = tf32r(v.x); v.y = tf32r(v.y); v.z = tf32r(v.z); v.w = tf32r(v.w);
    out[i] = v;
}

// ---- CSR build -------------------------------------------------------------

__global__ void hist_k(const int* __restrict__ ei, int* __restrict__ cnt,
                       int E, int N) {
    int i = blockIdx.x * blockDim.x + threadIdx.x;
    if (i >= E + N) return;
    int dst = (i < E) ? ei[E + i] : (i - E);
    atomicAdd(&cnt[dst], 1);
}

__global__ void scan1(const int* __restrict__ cnt, int* __restrict__ rp,
                      int* __restrict__ bsum, int N) {
    __shared__ int sh[1024];
    int tid = threadIdx.x, gid = blockIdx.x * 1024 + tid;
    int v = (gid < N) ? cnt[gid] : 0;
    sh[tid] = v;
    __syncthreads();
    for (int off = 1; off < 1024; off <<= 1) {
        int t = (tid >= off) ? sh[tid - off] : 0;
        __syncthreads();
        sh[tid] += t;
        __syncthreads();
    }
    if (gid < N) rp[gid] = sh[tid] - v;
    if (tid == 1023) bsum[blockIdx.x] = sh[1023];
}

__global__ void scan2(int* __restrict__ bsum, int nb) {
    __shared__ int sh[1024];
    int tid = threadIdx.x;
    int v = (tid < nb) ? bsum[tid] : 0;
    sh[tid] = v;
    __syncthreads();
    for (int off = 1; off < 1024; off <<= 1) {
        int t = (tid >= off) ? sh[tid - off] : 0;
        __syncthreads();
        sh[tid] += t;
        __syncthreads();
    }
    if (tid < nb) bsum[tid] = sh[tid] - v;
}

__global__ void scan3(int* __restrict__ rp, const int* __restrict__ bsum,
                      int* __restrict__ cursor, int N, int ET) {
    int gid = blockIdx.x * blockDim.x + threadIdx.x;
    if (gid < N) {
        int r = rp[gid] + bsum[gid >> 10];
        rp[gid] = r;
        cursor[gid] = r;
    }
    if (gid == N) rp[N] = ET;
}

__global__ void scatter_k(const int* __restrict__ ei, int* __restrict__ cursor,
                          int* __restrict__ ssrc, int E, int N) {
    int i = blockIdx.x * blockDim.x + threadIdx.x;
    if (i >= E + N) return;
    int src, dst;
    if (i < E) { src = ei[i]; dst = ei[E + i]; }
    else       { src = dst = i - E; }
    int p = atomicAdd(&cursor[dst], 1);
    ssrc[p] = src;
}

// ---- TF32 GEMM, cp.async 3-stage: C[M,N] = A[M,K]*B[N,K]^T -----------------

__global__ __launch_bounds__(256, 2)
void sgemm_tf32(const float* __restrict__ A, const float* __restrict__ B,
                float* __restrict__ Cm, int M, int N, int K) {
    constexpr int BM = 128, BN = 128, BK = 16, ST = 3, LDS = BK + 4;
    extern __shared__ float smn[];
    float (*As)[BM][LDS] = reinterpret_cast<float(*)[BM][LDS]>(smn);
    float (*Bs)[BN][LDS] =
        reinterpret_cast<float(*)[BN][LDS]>(smn + ST * BM * LDS);
    const int tid  = threadIdx.x;
    const int warp = tid >> 5, lane = tid & 31;
    const int wm = warp >> 2, wn = warp & 3;
    const int g = lane >> 2, t4 = lane & 3;
    const int bm = blockIdx.y * BM, bn = blockIdx.x * BN;
    const int r0 = tid >> 2, c40 = (tid & 3) << 2, r1 = r0 + 64;
    const bool pa0 = (bm + r0) < M, pa1 = (bm + r1) < M;

    auto load_stage = [&](int s, int k0) {
        cp16(&As[s][r0][c40], A + (size_t)(bm + r0) * K + k0 + c40, pa0);
        cp16(&As[s][r1][c40], A + (size_t)(bm + r1) * K + k0 + c40, pa1);
        cp16(&Bs[s][r0][c40], B + (size_t)(bn + r0) * K + k0 + c40, true);
        cp16(&Bs[s][r1][c40], B + (size_t)(bn + r1) * K + k0 + c40, true);
        CP_COMMIT();
    };

    float c[4][4][4] = {};

    load_stage(0, 0);
    load_stage(1, BK);
    int st = 0;

    for (int k0 = 0; k0 < K; k0 += BK) {
        asm volatile("cp.async.wait_group 1;");
        __syncthreads();
        int kn = k0 + 2 * BK;
        if (kn < K) load_stage(st == 0 ? 2 : st - 1, kn);
        else        CP_COMMIT();

        #pragma unroll
        for (int ks = 0; ks < BK; ks += 8) {
            uint32_t af[4][4], bf[4][2];
            #pragma unroll
            for (int mi = 0; mi < 4; mi++) {
                int row = wm * 64 + mi * 16;
                af[mi][0] = __float_as_uint(As[st][row + g][ks + t4]);
                af[mi][1] = __float_as_uint(As[st][row + g + 8][ks + t4]);
                af[mi][2] = __float_as_uint(As[st][row + g][ks + t4 + 4]);
                af[mi][3] = __float_as_uint(As[st][row + g + 8][ks + t4 + 4]);
            }
            #pragma unroll
            for (int ni = 0; ni < 4; ni++) {
                int col = wn * 32 + ni * 8;
                bf[ni][0] = __float_as_uint(Bs[st][col + g][ks + t4]);
                bf[ni][1] = __float_as_uint(Bs[st][col + g][ks + t4 + 4]);
            }
            #pragma unroll
            for (int mi = 0; mi < 4; mi++)
                #pragma unroll
                for (int ni = 0; ni < 4; ni++)
                    mma_tf32(c[mi][ni], af[mi], bf[ni]);
        }
        st = (st == ST - 1) ? 0 : st + 1;
    }

    #pragma unroll
    for (int mi = 0; mi < 4; mi++) {
        int row0 = bm + wm * 64 + mi * 16 + g;
        #pragma unroll
        for (int ni = 0; ni < 4; ni++) {
            int col = bn + wn * 32 + ni * 8 + t4 * 2;
            if (row0 < M)
                *reinterpret_cast<float2*>(Cm + (size_t)row0 * N + col) =
                    make_float2(c[mi][ni][0], c[mi][ni][1]);
            if (row0 + 8 < M)
                *reinterpret_cast<float2*>(Cm + (size_t)(row0 + 8) * N + col) =
                    make_float2(c[mi][ni][2], c[mi][ni][3]);
        }
    }
}

// ---- attention coefficients: s_n, d_n (warp per (node,head), float4) -------

__global__ void compute_sd(const float4* __restrict__ h,
                           const float4* __restrict__ a_src,
                           const float4* __restrict__ a_dst,
                           float* __restrict__ sn, float* __restrict__ dn,
                           int N, int H) {
    int w = (blockIdx.x * blockDim.x + threadIdx.x) >> 5;
    int lane = threadIdx.x & 31;
    if (w >= N * H) return;
    int n = w / H, hh = w - n * H;
    float4 v  = h[(size_t)n * H * 32 + hh * 32 + lane];
    float4 as = a_src[hh * 32 + lane];
    float4 ad = a_dst[hh * 32 + lane];
    float s = v.x * as.x + v.y * as.y + v.z * as.z + v.w * as.w;
    float d = v.x * ad.x + v.y * ad.y + v.z * ad.z + v.w * ad.w;
    #pragma unroll
    for (int o = 16; o; o >>= 1) {
        s += __shfl_down_sync(0xffffffffu, s, o);
        d += __shfl_down_sync(0xffffffffu, d, o);
    }
    if (lane == 0) { sn[w] = s; dn[w] = d; }
}

// ---- head-split gather aggregation: warp per node, HSPAN heads per pass ----
// Pass covers heads [h0, h0+HSPAN) of HTOT.  Per-pass gather working set =
// N * HSPAN*128 floats.  h reads evict_last; intermediate out evict_first.

template <int HSPAN>
__global__ void aggregate_k(const int* __restrict__ rp,
                            const int* __restrict__ ssrc,
                            const float4* __restrict__ hf,
                            const float* __restrict__ sn,
                            const float* __restrict__ dn,
                            const float4* __restrict__ bias, int act,
                            float4* __restrict__ outp, int N,
                            int HTOT, int h0) {
    constexpr int PER = HSPAN;               // float4 chunks per lane
    int n = (blockIdx.x * blockDim.x + threadIdx.x) >> 5;
    int lane = threadIdx.x & 31;
    if (n >= N) return;
    const int head = (HSPAN == 1) ? 0 : (lane >> 4);   // HSPAN==2: lane/16
    uint64_t pl = pol_last();
    uint64_t pf = pol_first();
    const int rowJ = HTOT * 32;              // float4 per full node row
    const int off  = h0 * 32 + lane * PER;   // this lane's chunk offset

    float dnv = (lane < HSPAN) ? dn[n * HTOT + h0 + lane] : 0.f;

    float4 acc[PER];
    #pragma unroll
    for (int it = 0; it < PER; it++) acc[it] = make_float4(0.f, 0.f, 0.f, 0.f);
    float den = 0.f;

    const int s0 = rp[n], s1 = rp[n + 1];
    int p = s0;
    for (; p + 1 < s1; p += 2) {
        int srcA = __ldg(ssrc + p);
        int srcB = __ldg(ssrc + p + 1);
        float exvA = 0.f, exvB = 0.f;
        if (lane < HSPAN) {
            float eA = sn[srcA * HTOT + h0 + lane] + dnv;
            float eB = sn[srcB * HTOT + h0 + lane] + dnv;
            eA = eA > 0.f ? eA : 0.2f * eA;
            eB = eB > 0.f ? eB : 0.2f * eB;
            exvA = __expf(eA);
            exvB = __expf(eB);
        }
        float exA = __shfl_sync(0xffffffffu, exvA, head);
        float exB = __shfl_sync(0xffffffffu, exvB, head);
        den += exA + exB;
        const float4* ra = hf + (size_t)srcA * rowJ + off;
        const float4* rb = hf + (size_t)srcB * rowJ + off;
        #pragma unroll
        for (int it = 0; it < PER; it++) {
            float4 va = ld4_hint(ra + it, pl);
            float4 vb = ld4_hint(rb + it, pl);
            acc[it].x += exA * va.x + exB * vb.x;
            acc[it].y += exA * va.y + exB * vb.y;
            acc[it].z += exA * va.z + exB * vb.z;
            acc[it].w += exA * va.w + exB * vb.w;
        }
    }
    if (p < s1) {
        int src = __ldg(ssrc + p);
        float exv = 0.f;
        if (lane < HSPAN) {
            float e = sn[src * HTOT + h0 + lane] + dnv;
            e = e > 0.f ? e : 0.2f * e;
            exv = __expf(e);
        }
        float ex = __shfl_sync(0xffffffffu, exv, head);
        den += ex;
        const float4* hrow = hf + (size_t)src * rowJ + off;
        #pragma unroll
        for (int it = 0; it < PER; it++) {
            float4 v = ld4_hint(hrow + it, pl);
            acc[it].x += ex * v.x; acc[it].y += ex * v.y;
            acc[it].z += ex * v.z; acc[it].w += ex * v.w;
        }
    }

    float sc = 1.f / (den + 1e-16f);
    float4* orow = outp + (size_t)n * rowJ + off;
    #pragma unroll
    for (int it = 0; it < PER; it++) {
        float4 bb = bias[off + it];
        float4 v;
        v.x = acc[it].x * sc + bb.x;
        v.y = acc[it].y * sc + bb.y;
        v.z = acc[it].z * sc + bb.z;
        v.w = acc[it].w * sc + bb.w;
        if (act) {
            v.x = v.x > 0.f ? v.x : (__expf(v.x) - 1.f);
            v.y = v.y > 0.f ? v.y : (__expf(v.y) - 1.f);
            v.z = v.z > 0.f ? v.z : (__expf(v.z) - 1.f);
            v.w = v.w > 0.f ? v.w : (__expf(v.w) - 1.f);
            v.x = tf32r(v.x); v.y = tf32r(v.y);
            v.z = tf32r(v.z); v.w = tf32r(v.w);
            st4_hint(orow + it, v, pf);
        } else {
            orow[it] = v;
        }
    }
}

// ---- MLP head --------------------------------------------------------------

__global__ __launch_bounds__(64)
void head_kernel(const float* __restrict__ emb, const float* __restrict__ Wh1,
                 const float* __restrict__ bh1, const float* __restrict__ Wh2,
                 const float* __restrict__ bh2, float* __restrict__ scores, int N) {
    int n = blockIdx.x;
    int j = threadIdx.x;
    __shared__ float er[128];
    __shared__ float zs[64];
    er[j]      = emb[(size_t)n * 128 + j];
    er[j + 64] = emb[(size_t)n * 128 + 64 + j];
    __syncthreads();
    const float* w = Wh1 + j * 128;
    float s = 0.f;
    #pragma unroll 8
    for (int k = 0; k < 128; k++) s += er[k] * w[k];
    s += bh1[j];
    s = fmaxf(s, 0.f);
    zs[j] = s * Wh2[j];
    __syncthreads();
    if (j < 32) {
        float v = zs[j] + zs[j + 32];
        #pragma unroll
        for (int o = 16; o; o >>= 1) v += __shfl_down_sync(0xffffffffu, v, o);
        if (j == 0) scores[n] = 1.f / (1.f + __expf(-(v + bh2[0])));
    }
}

// ---------------------------------------------------------------------------

extern "C" void kernel_launch(void* const* d_in, const int* in_sizes, int n_in,
                              void* d_out, int out_size) {
    const float* x  = (const float*)d_in[0];
    const int*   ei = (const int*)d_in[1];
    const float *W1 = (const float*)d_in[2],  *as1 = (const float*)d_in[3],
                *ad1 = (const float*)d_in[4], *b1 = (const float*)d_in[5];
    const float *W2 = (const float*)d_in[6],  *as2 = (const float*)d_in[7],
                *ad2 = (const float*)d_in[8], *b2 = (const float*)d_in[9];
    const float *W3 = (const float*)d_in[10], *as3 = (const float*)d_in[11],
                *ad3 = (const float*)d_in[12], *b3 = (const float*)d_in[13];
    const float *Wh1 = (const float*)d_in[14], *bh1 = (const float*)d_in[15],
                *Wh2 = (const float*)d_in[16], *bh2 = (const float*)d_in[17];
    float* out = (float*)d_out;

    const int N = in_sizes[0] / 256;
    const int E = in_sizes[1] / 2;
    const int ET = E + N;

    float4 *gh4, *gout4, *wc4;
    float *snp, *dnp;
    int *cnt, *rp, *cursor, *ssrc, *bsum;
    cudaGetSymbolAddress((void**)&gh4,    g_h_buf4);
    cudaGetSymbolAddress((void**)&gout4,  g_out_buf4);
    cudaGetSymbolAddress((void**)&wc4,    g_wc4);
    cudaGetSymbolAddress((void**)&snp,    g_sn_buf);
    cudaGetSymbolAddress((void**)&dnp,    g_dn_buf);
    cudaGetSymbolAddress((void**)&cnt,    g_cnt);
    cudaGetSymbolAddress((void**)&rp,     g_rp);
    cudaGetSymbolAddress((void**)&cursor, g_cursor);
    cudaGetSymbolAddress((void**)&ssrc,   g_ssrc);
    cudaGetSymbolAddress((void**)&bsum,   g_bsum);
    float* gout = (float*)gout4;

    auto cdiv = [](int a, int b) { return (a + b - 1) / b; };

    constexpr int SMEM_GEMM = 3 * 128 * 20 * 2 * 4;   // 61440 B
    cudaFuncSetAttribute(sgemm_tf32,
                         cudaFuncAttributeMaxDynamicSharedMemorySize, SMEM_GEMM);

    // ---- pre-round weights + x to tf32 bits ----
    float* wc1 = (float*)wc4;
    float* wc2 = wc1 + 131072;
    float* wc3 = wc2 + 262144;
    cvt4_k<<<cdiv(131072 / 4, 256), 256>>>((const float4*)W1, (float4*)wc1, 131072 / 4);
    cvt4_k<<<cdiv(262144 / 4, 256), 256>>>((const float4*)W2, (float4*)wc2, 262144 / 4);
    cvt4_k<<<cdiv(65536 / 4, 256), 256>>>((const float4*)W3, (float4*)wc3, 65536 / 4);
    float* xc = gout;
    cvt4_k<<<cdiv(N * 64, 256), 256>>>((const float4*)x, (float4*)xc, N * 64);

    // ---- CSR build (once; reused by all 3 layers) ----
    const int nb = cdiv(N, 1024);
    cudaMemsetAsync(cnt, 0, (size_t)N * 4);
    hist_k<<<cdiv(ET, 256), 256>>>(ei, cnt, E, N);
    scan1<<<nb, 1024>>>(cnt, rp, bsum, N);
    scan2<<<1, 1024>>>(bsum, nb);
    scan3<<<cdiv(N + 1, 256), 256>>>(rp, bsum, cursor, N, ET);
    scatter_k<<<cdiv(ET, 256), 256>>>(ei, cursor, ssrc, E, N);

    // ---- generic GAT layer ----
    auto run_layer = [&](const float* fin, int Fin, const float* W,
                         const float* as, const float* ad, const float* bb,
                         int H, int act, float* finalout) {
        const int HC = H * 128;
        dim3 gg(cdiv(HC, 128), cdiv(N, 128));
        sgemm_tf32<<<gg, 256, SMEM_GEMM>>>(fin, W, (float*)gh4, N, HC, Fin);
        compute_sd<<<cdiv(N * H * 32, 256), 256>>>(
            (const float4*)gh4, (const float4*)as, (const float4*)ad,
            snp, dnp, N, H);
        int agg_grid = cdiv(N * 32, 256);
        if (H == 4) {
            // two passes over head pairs: per-pass gather set fits in L2
            aggregate_k<2><<<agg_grid, 256>>>(
                rp, ssrc, gh4, snp, dnp, (const float4*)bb, act,
                (float4*)finalout, N, 4, 0);
            aggregate_k<2><<<agg_grid, 256>>>(
                rp, ssrc, gh4, snp, dnp, (const float4*)bb, act,
                (float4*)finalout, N, 4, 2);
        } else {
            aggregate_k<1><<<agg_grid, 256>>>(
                rp, ssrc, gh4, snp, dnp, (const float4*)bb, act,
                (float4*)finalout, N, 1, 0);
        }
    };

    run_layer(xc,   256, wc1, as1, ad1, b1, 4, 1, gout);
    run_layer(gout, 512, wc2, as2, ad2, b2, 4, 1, gout);
    run_layer(gout, 512, wc3, as3, ad3, b3, 1, 0, out);

    head_kernel<<<N, 64>>>(out, Wh1, bh1, Wh2, bh2, out + (size_t)N * 128, N);
}